// round 8
// baseline (speedup 1.0000x reference)
#include <cuda_runtime.h>
#include <cuda_bf16.h>
#include <math.h>

#define NN 10000      // nodes
#define TT 12         // seq len
#define FIN 16        // in channels
#define HH 64         // hidden
#define K3 192        // 3*H
#define NE 160000     // edges
#define NT (NN*TT)    // 120000 rows
#define MB 80         // nodes per block (10000 = 125 * 80)
#define GRID_REC 125

typedef unsigned int u32;
typedef unsigned long long u64;

// ---------------- scratch (device globals; no allocation allowed) ----------
__device__ float g_deg[NN];
__device__ float g_agg[NN * TT * FIN];
__device__ uint2 g_ha2[NN * TT * (HH / 2)];   // packed bf16 {hi-pair, lo-pair}

// ---------------- helpers ----------------------------------------------------
__device__ __forceinline__ float tanh_fast(float x) {
    float y; asm("tanh.approx.f32 %0, %1;" : "=f"(y) : "f"(x)); return y;
}
__device__ __forceinline__ float sigmoid_fast(float x) {
    return fmaf(0.5f, tanh_fast(0.5f * x), 0.5f);
}
__device__ __forceinline__ u32 pack2(__nv_bfloat16 a, __nv_bfloat16 b) {
    return (u32)__bfloat16_as_ushort(a) | ((u32)__bfloat16_as_ushort(b) << 16);
}
__device__ __forceinline__ void split_bf16(float v, __nv_bfloat16& hi, __nv_bfloat16& lo) {
    hi = __float2bfloat16(v);
    lo = __float2bfloat16(v - __bfloat162float(hi));
}
__device__ __forceinline__ void mma16816(float* c, const u32* a, u32 b0, u32 b1) {
    asm volatile(
        "mma.sync.aligned.m16n8k16.row.col.f32.bf16.bf16.f32 "
        "{%0,%1,%2,%3}, {%4,%5,%6,%7}, {%8,%9}, {%0,%1,%2,%3};"
        : "+f"(c[0]), "+f"(c[1]), "+f"(c[2]), "+f"(c[3])
        : "r"(a[0]), "r"(a[1]), "r"(a[2]), "r"(a[3]), "r"(b0), "r"(b1));
}
__device__ __forceinline__ void ldm4(u32* r, u32 saddr) {
    asm volatile("ldmatrix.sync.aligned.m8n8.x4.shared.b16 {%0,%1,%2,%3}, [%4];"
                 : "=r"(r[0]), "=r"(r[1]), "=r"(r[2]), "=r"(r[3]) : "r"(saddr));
}

// ---------------- degree / prep --------------------------------------------
__global__ void k_deg_init() {
    int i = blockIdx.x * blockDim.x + threadIdx.x;
    if (i < NN) g_deg[i] = 1.0f;
}
__global__ void k_deg_edge(const int* __restrict__ ei) {
    int e = blockIdx.x * blockDim.x + threadIdx.x;
    if (e < NE) atomicAdd(&g_deg[ei[NE + e]], 1.0f);
}
__global__ void k_agg_init(const float* __restrict__ x) {
    int idx = blockIdx.x * blockDim.x + threadIdx.x;
    if (idx >= NN * TT * 4) return;
    int n = idx / (TT * 4);
    int r = idx - n * (TT * 4);
    int t = r >> 2, f4 = r & 3;
    float di = rsqrtf(g_deg[n]);
    float c = di * di;
    float4 v = reinterpret_cast<const float4*>(x)[((size_t)t * NN + n) * 4 + f4];
    v.x *= c; v.y *= c; v.z *= c; v.w *= c;
    reinterpret_cast<float4*>(g_agg)[idx] = v;
}
__global__ void k_edge_agg(const int* __restrict__ ei, const float* __restrict__ x) {
    int gt = blockIdx.x * blockDim.x + threadIdx.x;
    int e = gt >> 5, lane = gt & 31;
    if (e >= NE) return;
    int s = ei[e];
    int d = ei[NE + e];
    float c = rsqrtf(g_deg[s]) * rsqrtf(g_deg[d]);
    const float4* x4 = reinterpret_cast<const float4*>(x);
    float4* dst4 = reinterpret_cast<float4*>(&g_agg[(size_t)d * (TT * FIN)]);
#pragma unroll
    for (int g = lane; g < 48; g += 32) {
        int t = g >> 2, f4 = g & 3;
        float4 v = x4[((size_t)t * NN + s) * 4 + f4];
        asm volatile("red.global.add.v4.f32 [%0], {%1, %2, %3, %4};"
                     :: "l"(dst4 + g), "f"(v.x * c), "f"(v.y * c), "f"(v.z * c), "f"(v.w * c)
                     : "memory");
    }
}

// ---------------- fused HMMA GRU layers --------------------------------------
#define OFF_AHI 0
#define OFF_ALO 20480
#define OFF_GRZ 40960      // fp32 [80][128], swizzled
#define OFF_GX  81920      // fp32 [80][64]
#define OFF_GH  102400
#define OFF_HS  122880     // fp32 h state [80][64]
#define OFF_B   143360     // biases: 256 floats
#define OFF_EXT 144384
#define SMEM_L0 (OFF_EXT + 4096 + 256)
#define SMEM_L1 (OFF_EXT + 20480 + 640 + 256 + 256 + 16)

// 3-term m-tile (n gates): full hi/lo compensation
template<int KKS, int NTS>
__device__ __forceinline__ void mma_m_tile3(
    u32 ahi_base, u32 alo_base, int kbyte, int swrow,
    const u32* bh, const u32* bl, float* acc)
{
    float hh[NTS * 4], hl[NTS * 4], lh[NTS * 4];
#pragma unroll
    for (int q = 0; q < NTS * 4; q++) { hh[q] = 0.f; hl[q] = 0.f; lh[q] = 0.f; }
#pragma unroll
    for (int kk = 0; kk < KKS; kk++) {
        u32 off = (u32)((kk * 32 + kbyte) ^ swrow);
        u32 ah[4], al[4];
        ldm4(ah, ahi_base + off);
        ldm4(al, alo_base + off);
#pragma unroll
        for (int nt = 0; nt < NTS; nt++) {
            int f = kk * NTS + nt;
            mma16816(hh + nt * 4, ah, bh[2 * f], bh[2 * f + 1]);
            mma16816(hl + nt * 4, ah, bl[2 * f], bl[2 * f + 1]);
            mma16816(lh + nt * 4, al, bh[2 * f], bh[2 * f + 1]);
        }
    }
#pragma unroll
    for (int q = 0; q < NTS * 4; q++) acc[q] = hh[q] + hl[q] + lh[q];
}

// 2-term m-tile (r/z gates): drop a_lo*b_hi correction (sigmoid-damped path)
template<int KKS, int NTS>
__device__ __forceinline__ void mma_m_tile2(
    u32 ahi_base, int kbyte, int swrow,
    const u32* bh, const u32* bl, float* acc)
{
    float hh[NTS * 4], hl[NTS * 4];
#pragma unroll
    for (int q = 0; q < NTS * 4; q++) { hh[q] = 0.f; hl[q] = 0.f; }
#pragma unroll
    for (int kk = 0; kk < KKS; kk++) {
        u32 off = (u32)((kk * 32 + kbyte) ^ swrow);
        u32 ah[4];
        ldm4(ah, ahi_base + off);
#pragma unroll
        for (int nt = 0; nt < NTS; nt++) {
            int f = kk * NTS + nt;
            mma16816(hh + nt * 4, ah, bh[2 * f], bh[2 * f + 1]);
            mma16816(hl + nt * 4, ah, bl[2 * f], bl[2 * f + 1]);
        }
    }
#pragma unroll
    for (int q = 0; q < NTS * 4; q++) acc[q] = hh[q] + hl[q];
}

template<int L>
__global__ __launch_bounds__(384, 1) void k_rec(
    const float* __restrict__ wih, const float* __restrict__ whh,
    const float* __restrict__ bih, const float* __restrict__ bhh,
    const float* __restrict__ gwp, const float* __restrict__ gbp,
    const float* __restrict__ awp, const float* __restrict__ abp,
    const float* __restrict__ fwp, const float* __restrict__ fbp,
    const float* __restrict__ x,   float* __restrict__ outv)
{
    extern __shared__ __align__(16) char sm[];
    char* AHI = sm + OFF_AHI;
    char* ALO = sm + OFF_ALO;
    char* GRZ = sm + OFF_GRZ;
    char* GX  = sm + OFF_GX;
    char* GH  = sm + OFF_GH;
    float* hS   = (float*)(sm + OFF_HS);
    float* bias = (float*)(sm + OFF_B);
    float* gwS = (float*)(sm + OFF_EXT);
    float* gbS = (float*)(sm + OFF_EXT + 4096);
    float* ctx = (float*)(sm + OFF_EXT);
    float* mS  = (float*)(sm + OFF_EXT + 20480);
    float* ZS  = (float*)(sm + OFF_EXT + 20480 + 320);
    float* awS = (float*)(sm + OFF_EXT + 21120);
    float* fwS = (float*)(sm + OFF_EXT + 21376);
    float* scS = (float*)(sm + OFF_EXT + 21632);

    int tid = threadIdx.x, wid = tid >> 5, lid = tid & 31;
    int g = lid >> 2, tg = lid & 3;
    int node0 = blockIdx.x * MB;

    if (tid < 128) bias[tid] = bih[tid] + bhh[tid];
    else if (tid < 192) bias[tid] = bih[tid];
    else if (tid < 256) bias[tid] = bhh[tid - 64];

    if (L == 0) {
        for (int i = tid; i < FIN * HH; i += 384) gwS[i] = gwp[i];
        if (tid < 64) gbS[tid] = gbp[tid];
    } else {
        for (int i = tid; i < MB * 64; i += 384) ctx[i] = 0.0f;
        if (tid < MB) { mS[tid] = -3.0e38f; ZS[tid] = 0.0f; }
        if (tid < 64) { awS[tid] = awp[tid]; fwS[tid] = fwp[tid]; }
        if (tid == 0) scS[0] = abp[0];
    }

    {
        uint4 z = make_uint4(0, 0, 0, 0);
        for (int i = tid; i < 2560; i += 384) {
            ((uint4*)AHI)[i] = z;
            ((uint4*)ALO)[i] = z;
        }
        for (int i = tid; i < MB * 64; i += 384) hS[i] = 0.0f;
    }

    bool is_rz = wid < 8;
    int role = is_rz ? 0 : (wid < 10 ? 1 : 2);

    // persistent B fragments (hi/lo)
    u32 bh[32], bl[32];
#pragma unroll
    for (int f = 0; f < 16; f++) {
        int kk = is_rz ? (f >> 1) : (f >> 2);
        int nt = is_rz ? (f & 1)  : (f & 3);
        int nrow;
        if (role == 0)      nrow = wid * 16 + nt * 8 + g;
        else if (role == 1) nrow = 128 + (wid - 8) * 32 + nt * 8 + g;
        else                nrow = 128 + (wid - 10) * 32 + nt * 8 + g;
#pragma unroll
        for (int r = 0; r < 2; r++) {
            int k = kk * 16 + tg * 2 + r * 8;
            float w0, w1;
            if (role == 0) {
                if (k < 64) { w0 = wih[nrow * 64 + k];      w1 = wih[nrow * 64 + k + 1]; }
                else        { w0 = whh[nrow * 64 + k - 64]; w1 = whh[nrow * 64 + k - 63]; }
            } else if (role == 1) {
                w0 = wih[nrow * 64 + k]; w1 = wih[nrow * 64 + k + 1];
            } else {
                w0 = whh[nrow * 64 + k]; w1 = whh[nrow * 64 + k + 1];
            }
            __nv_bfloat16 h0, l0, h1, l1;
            split_bf16(w0, h0, l0);
            split_bf16(w1, h1, l1);
            bh[2 * f + r] = pack2(h0, h1);
            bl[2 * f + r] = pack2(l0, l1);
        }
    }

    int aoff = (role == 2) ? 128 : 0;
    int quad = lid >> 3;
    int rloc = (lid & 7) + ((quad & 1) << 3);
    int kbyte = (quad >> 1) << 4;
    int swrow = (rloc & 7) << 4;
    u32 AHI_s = (u32)__cvta_generic_to_shared(AHI);
    u32 ALO_s = (u32)__cvta_generic_to_shared(ALO);

    const uint4* in16 = reinterpret_cast<const uint4*>(g_ha2);
    float aw0 = 0.f, aw1 = 0.f, ab = 0.f;
    __syncthreads();
    if (L == 1) { aw0 = awS[2 * lid]; aw1 = awS[2 * lid + 1]; ab = scS[0]; }

    for (int t = 0; t < TT; t++) {
        // ---- stage X(t) into A tile (bf16 hi/lo, swizzled) ----
        if (L == 0) {
            for (int i = tid; i < MB * 16; i += 384) {
                int m = i >> 4, j = i & 15;
                const float4* ar = reinterpret_cast<const float4*>(
                    &g_agg[(((size_t)(node0 + m)) * TT + t) * 16]);
                float4 a0 = ar[0], a1 = ar[1], a2 = ar[2], a3 = ar[3];
                float s0 = gbS[4 * j], s1 = gbS[4 * j + 1], s2 = gbS[4 * j + 2], s3 = gbS[4 * j + 3];
#pragma unroll
                for (int f = 0; f < 16; f++) {
                    float av;
                    if (f < 4) av = ((const float*)&a0)[f];
                    else if (f < 8) av = ((const float*)&a1)[f - 4];
                    else if (f < 12) av = ((const float*)&a2)[f - 8];
                    else av = ((const float*)&a3)[f - 12];
                    const float4 wv = reinterpret_cast<const float4*>(gwS)[f * 16 + j];
                    s0 = fmaf(av, wv.x, s0);
                    s1 = fmaf(av, wv.y, s1);
                    s2 = fmaf(av, wv.z, s2);
                    s3 = fmaf(av, wv.w, s3);
                }
                s0 = fmaxf(s0, 0.f); s1 = fmaxf(s1, 0.f);
                s2 = fmaxf(s2, 0.f); s3 = fmaxf(s3, 0.f);
                __nv_bfloat16 e0, f0, e1, f1, e2, f2, e3, f3;
                split_bf16(s0, e0, f0); split_bf16(s1, e1, f1);
                split_bf16(s2, e2, f2); split_bf16(s3, e3, f3);
                uint2 phv; phv.x = pack2(e0, e1); phv.y = pack2(e2, e3);
                uint2 plv; plv.x = pack2(f0, f1); plv.y = pack2(f2, f3);
                int byt = m * 256 + ((8 * j) ^ ((m & 7) << 4));
                *(uint2*)(AHI + byt) = phv;
                *(uint2*)(ALO + byt) = plv;
            }
        } else {
            // raw copy of pre-split h1: uint4 = {hi_p, lo_p, hi_p1, lo_p1}
            for (int i = tid; i < MB * 16; i += 384) {
                int m = i >> 4, j = i & 15;
                uint4 v = in16[((size_t)(node0 + m) * TT + t) * 16 + j];
                int byt = m * 256 + ((8 * j) ^ ((m & 7) << 4));
                *(uint2*)(AHI + byt) = make_uint2(v.x, v.z);
                *(uint2*)(ALO + byt) = make_uint2(v.y, v.w);
            }
        }
        __syncthreads();

        // ---- MMA: 5 m-tiles of 16 rows ----
        for (int m = 0; m < 5; m++) {
            float acc[16];
            u32 rowb = (u32)((m * 16 + rloc) * 256 + aoff);
            if (is_rz) mma_m_tile2<8, 2>(AHI_s + rowb, kbyte, swrow, bh, bl, acc);
            else       mma_m_tile3<4, 4>(AHI_s + rowb, ALO_s + rowb, kbyte, swrow, bh, bl, acc);

            int row0 = m * 16 + g;
            int swG = g << 5;
            if (role == 0) {
#pragma unroll
                for (int nt = 0; nt < 2; nt++) {
                    int b = (4 * (wid * 16 + nt * 8 + tg * 2)) ^ swG;
                    *(float2*)(GRZ + row0 * 512 + b)       = make_float2(acc[nt * 4 + 0], acc[nt * 4 + 1]);
                    *(float2*)(GRZ + (row0 + 8) * 512 + b) = make_float2(acc[nt * 4 + 2], acc[nt * 4 + 3]);
                }
            } else {
                char* Gp = (role == 1) ? GX : GH;
                int wb = (role == 1) ? (wid - 8) : (wid - 10);
#pragma unroll
                for (int nt = 0; nt < 4; nt++) {
                    int b = (4 * (wb * 32 + nt * 8 + tg * 2)) ^ swG;
                    *(float2*)(Gp + row0 * 256 + b)       = make_float2(acc[nt * 4 + 0], acc[nt * 4 + 1]);
                    *(float2*)(Gp + (row0 + 8) * 256 + b) = make_float2(acc[nt * 4 + 2], acc[nt * 4 + 3]);
                }
            }
        }
        __syncthreads();

        // ---- gates (+ L1: online-softmax attention) ----
        for (int p = tid; p < MB * 32; p += 384) {
            int row = p >> 5, jp = p & 31;
            int sw = (row & 7) << 5;
            int o = (8 * jp) ^ sw;
            float2 rv = *(float2*)(GRZ + row * 512 + o);
            float2 zv = *(float2*)(GRZ + row * 512 + 256 + o);
            float2 xv = *(float2*)(GX + row * 256 + o);
            float2 hv = *(float2*)(GH + row * 256 + o);
            int i0 = 2 * jp;
            float hp0 = hS[row * 64 + i0], hp1 = hS[row * 64 + i0 + 1];
            float r0 = sigmoid_fast(rv.x + bias[i0]);
            float r1 = sigmoid_fast(rv.y + bias[i0 + 1]);
            float z0 = sigmoid_fast(zv.x + bias[64 + i0]);
            float z1 = sigmoid_fast(zv.y + bias[64 + i0 + 1]);
            float n0 = tanh_fast(xv.x + bias[128 + i0]     + r0 * (hv.x + bias[192 + i0]));
            float n1 = tanh_fast(xv.y + bias[128 + i0 + 1] + r1 * (hv.y + bias[192 + i0 + 1]));
            float o0 = fmaf(z0, hp0 - n0, n0);
            float o1 = fmaf(z1, hp1 - n1, n1);
            hS[row * 64 + i0] = o0;
            hS[row * 64 + i0 + 1] = o1;
            __nv_bfloat16 e0, f0, e1, f1;
            split_bf16(o0, e0, f0);
            split_bf16(o1, e1, f1);
            u32 hip = pack2(e0, e1), lop = pack2(f0, f1);
            int ba = row * 256 + 128 + ((4 * jp) ^ ((row & 7) << 4));
            *(u32*)(AHI + ba) = hip;
            *(u32*)(ALO + ba) = lop;
            if (L == 0) {
                g_ha2[((size_t)(node0 + row) * TT + t) * 32 + jp] = make_uint2(hip, lop);
            } else {
                float sc = o0 * aw0 + o1 * aw1;
#pragma unroll
                for (int of = 16; of > 0; of >>= 1) sc += __shfl_xor_sync(0xffffffffu, sc, of);
                sc += ab;
                float m_old = mS[row];
                float mn = fmaxf(m_old, sc);
                float ea = __expf(m_old - mn);
                float eb = __expf(sc - mn);
                ctx[row * 64 + i0]     = ctx[row * 64 + i0]     * ea + eb * o0;
                ctx[row * 64 + i0 + 1] = ctx[row * 64 + i0 + 1] * ea + eb * o1;
                if (jp == 0) { mS[row] = mn; ZS[row] = ZS[row] * ea + eb; }
            }
        }
        __syncthreads();
    }

    if (L == 1) {
        float fw0 = fwS[2 * lid], fw1 = fwS[2 * lid + 1];
        for (int row = wid; row < MB; row += 12) {
            float v = ctx[row * 64 + 2 * lid] * fw0 + ctx[row * 64 + 2 * lid + 1] * fw1;
#pragma unroll
            for (int of = 16; of > 0; of >>= 1) v += __shfl_xor_sync(0xffffffffu, v, of);
            if (lid == 0) {
                int node = node0 + row;
                float last = x[((size_t)(TT - 1) * NN + node) * FIN];
                outv[node] = last + v / ZS[row] + fbp[0];
            }
        }
    }
}

// ---------------- launch ----------------------------------------------------
extern "C" void kernel_launch(void* const* d_in, const int* in_sizes, int n_in,
                              void* d_out, int out_size) {
    const float* x      = (const float*)d_in[0];
    const int*   ei     = (const int*)  d_in[1];
    const float* gcn_w  = (const float*)d_in[2];
    const float* gcn_b  = (const float*)d_in[3];
    const float* w_ih0  = (const float*)d_in[4];
    const float* w_hh0  = (const float*)d_in[5];
    const float* b_ih0  = (const float*)d_in[6];
    const float* b_hh0  = (const float*)d_in[7];
    const float* w_ih1  = (const float*)d_in[8];
    const float* w_hh1  = (const float*)d_in[9];
    const float* b_ih1  = (const float*)d_in[10];
    const float* b_hh1  = (const float*)d_in[11];
    const float* attn_w = (const float*)d_in[12];
    const float* attn_b = (const float*)d_in[13];
    const float* fc_w   = (const float*)d_in[14];
    const float* fc_b   = (const float*)d_in[15];
    float* out = (float*)d_out;

    cudaFuncSetAttribute(k_rec<0>, cudaFuncAttributeMaxDynamicSharedMemorySize, SMEM_L0);
    cudaFuncSetAttribute(k_rec<1>, cudaFuncAttributeMaxDynamicSharedMemorySize, SMEM_L1);

    k_deg_init<<<(NN + 255) / 256, 256>>>();
    k_deg_edge<<<(NE + 255) / 256, 256>>>(ei);
    k_agg_init<<<(NN * TT * 4 + 255) / 256, 256>>>(x);
    k_edge_agg<<<(NE * 32 + 255) / 256, 256>>>(ei, x);

    k_rec<0><<<GRID_REC, 384, SMEM_L0>>>(w_ih0, w_hh0, b_ih0, b_hh0,
                                         gcn_w, gcn_b, nullptr, nullptr, nullptr, nullptr,
                                         x, nullptr);
    k_rec<1><<<GRID_REC, 384, SMEM_L1>>>(w_ih1, w_hh1, b_ih1, b_hh1,
                                         nullptr, nullptr, attn_w, attn_b, fc_w, fc_b,
                                         x, out);
}

// round 9
// speedup vs baseline: 1.5365x; 1.5365x over previous
#include <cuda_runtime.h>
#include <cuda_bf16.h>
#include <math.h>

#define NN 10000      // nodes
#define TT 12         // seq len
#define FIN 16        // in channels
#define HH 64         // hidden
#define K3 192        // 3*H
#define NE 160000     // edges
#define NT (NN*TT)    // 120000 rows
#define MB 80         // nodes per block (10000 = 125 * 80)
#define GRID_REC 125

typedef unsigned int u32;
typedef unsigned long long u64;

// ---------------- scratch (device globals; no allocation allowed) ----------
__device__ float g_deg[NN];
__device__ float g_agg[NN * TT * FIN];
__device__ uint2 g_ha2[NN * TT * (HH / 2)];   // packed bf16 {hi-pair, lo-pair}

// ---------------- helpers ----------------------------------------------------
__device__ __forceinline__ float tanh_fast(float x) {
    float y; asm("tanh.approx.f32 %0, %1;" : "=f"(y) : "f"(x)); return y;
}
__device__ __forceinline__ float sigmoid_fast(float x) {
    return fmaf(0.5f, tanh_fast(0.5f * x), 0.5f);
}
__device__ __forceinline__ u32 pack2(__nv_bfloat16 a, __nv_bfloat16 b) {
    return (u32)__bfloat16_as_ushort(a) | ((u32)__bfloat16_as_ushort(b) << 16);
}
__device__ __forceinline__ void split_bf16(float v, __nv_bfloat16& hi, __nv_bfloat16& lo) {
    hi = __float2bfloat16(v);
    lo = __float2bfloat16(v - __bfloat162float(hi));
}
__device__ __forceinline__ void mma16816(float* c, const u32* a, u32 b0, u32 b1) {
    asm volatile(
        "mma.sync.aligned.m16n8k16.row.col.f32.bf16.bf16.f32 "
        "{%0,%1,%2,%3}, {%4,%5,%6,%7}, {%8,%9}, {%0,%1,%2,%3};"
        : "+f"(c[0]), "+f"(c[1]), "+f"(c[2]), "+f"(c[3])
        : "r"(a[0]), "r"(a[1]), "r"(a[2]), "r"(a[3]), "r"(b0), "r"(b1));
}
__device__ __forceinline__ void ldm4(u32* r, u32 saddr) {
    asm volatile("ldmatrix.sync.aligned.m8n8.x4.shared.b16 {%0,%1,%2,%3}, [%4];"
                 : "=r"(r[0]), "=r"(r[1]), "=r"(r[2]), "=r"(r[3]) : "r"(saddr));
}

// ---------------- degree / prep --------------------------------------------
__global__ void k_deg_init() {
    int i = blockIdx.x * blockDim.x + threadIdx.x;
    if (i < NN) g_deg[i] = 1.0f;
}
__global__ void k_deg_edge(const int* __restrict__ ei) {
    int e = blockIdx.x * blockDim.x + threadIdx.x;
    if (e < NE) atomicAdd(&g_deg[ei[NE + e]], 1.0f);
}
__global__ void k_agg_init(const float* __restrict__ x) {
    int idx = blockIdx.x * blockDim.x + threadIdx.x;
    if (idx >= NN * TT * 4) return;
    int n = idx / (TT * 4);
    int r = idx - n * (TT * 4);
    int t = r >> 2, f4 = r & 3;
    float di = rsqrtf(g_deg[n]);
    float c = di * di;
    float4 v = reinterpret_cast<const float4*>(x)[((size_t)t * NN + n) * 4 + f4];
    v.x *= c; v.y *= c; v.z *= c; v.w *= c;
    reinterpret_cast<float4*>(g_agg)[idx] = v;
}
__global__ void k_edge_agg(const int* __restrict__ ei, const float* __restrict__ x) {
    int gt = blockIdx.x * blockDim.x + threadIdx.x;
    int e = gt >> 5, lane = gt & 31;
    if (e >= NE) return;
    int s = ei[e];
    int d = ei[NE + e];
    float c = rsqrtf(g_deg[s]) * rsqrtf(g_deg[d]);
    const float4* x4 = reinterpret_cast<const float4*>(x);
    float4* dst4 = reinterpret_cast<float4*>(&g_agg[(size_t)d * (TT * FIN)]);
#pragma unroll
    for (int g = lane; g < 48; g += 32) {
        int t = g >> 2, f4 = g & 3;
        float4 v = x4[((size_t)t * NN + s) * 4 + f4];
        asm volatile("red.global.add.v4.f32 [%0], {%1, %2, %3, %4};"
                     :: "l"(dst4 + g), "f"(v.x * c), "f"(v.y * c), "f"(v.z * c), "f"(v.w * c)
                     : "memory");
    }
}

// ---------------- fused HMMA GRU layers --------------------------------------
#define OFF_AHI 0
#define OFF_ALO 20480
#define OFF_GRZ 40960      // fp32 [80][128], swizzled
#define OFF_GX  81920      // fp32 [80][64]
#define OFF_GH  102400
#define OFF_HS  122880     // fp32 h state [80][64]
#define OFF_B   143360     // biases: 256 floats
#define OFF_EXT 144384
#define SMEM_L0 (OFF_EXT + 4096 + 256)
#define SMEM_L1 (OFF_EXT + 20480 + 640 + 256 + 256 + 16)

// 3-term m-tile (n gates): full hi/lo compensation
template<int KKS, int NTS>
__device__ __forceinline__ void mma_m_tile3(
    u32 ahi_base, u32 alo_base, int kbyte, int swrow,
    const u32* bh, const u32* bl, float* acc)
{
    float hh[NTS * 4], hl[NTS * 4], lh[NTS * 4];
#pragma unroll
    for (int q = 0; q < NTS * 4; q++) { hh[q] = 0.f; hl[q] = 0.f; lh[q] = 0.f; }
#pragma unroll
    for (int kk = 0; kk < KKS; kk++) {
        u32 off = (u32)((kk * 32 + kbyte) ^ swrow);
        u32 ah[4], al[4];
        ldm4(ah, ahi_base + off);
        ldm4(al, alo_base + off);
#pragma unroll
        for (int nt = 0; nt < NTS; nt++) {
            int f = kk * NTS + nt;
            mma16816(hh + nt * 4, ah, bh[2 * f], bh[2 * f + 1]);
            mma16816(hl + nt * 4, ah, bl[2 * f], bl[2 * f + 1]);
            mma16816(lh + nt * 4, al, bh[2 * f], bh[2 * f + 1]);
        }
    }
#pragma unroll
    for (int q = 0; q < NTS * 4; q++) acc[q] = hh[q] + hl[q] + lh[q];
}

// 2-term m-tile (r/z gates): drop a_lo*b_hi correction (sigmoid-damped path)
template<int KKS, int NTS>
__device__ __forceinline__ void mma_m_tile2(
    u32 ahi_base, int kbyte, int swrow,
    const u32* bh, const u32* bl, float* acc)
{
    float hh[NTS * 4], hl[NTS * 4];
#pragma unroll
    for (int q = 0; q < NTS * 4; q++) { hh[q] = 0.f; hl[q] = 0.f; }
#pragma unroll
    for (int kk = 0; kk < KKS; kk++) {
        u32 off = (u32)((kk * 32 + kbyte) ^ swrow);
        u32 ah[4];
        ldm4(ah, ahi_base + off);
#pragma unroll
        for (int nt = 0; nt < NTS; nt++) {
            int f = kk * NTS + nt;
            mma16816(hh + nt * 4, ah, bh[2 * f], bh[2 * f + 1]);
            mma16816(hl + nt * 4, ah, bl[2 * f], bl[2 * f + 1]);
        }
    }
#pragma unroll
    for (int q = 0; q < NTS * 4; q++) acc[q] = hh[q] + hl[q];
}

template<int L>
__global__ __launch_bounds__(384, 1) void k_rec(
    const float* __restrict__ wih, const float* __restrict__ whh,
    const float* __restrict__ bih, const float* __restrict__ bhh,
    const float* __restrict__ gwp, const float* __restrict__ gbp,
    const float* __restrict__ awp, const float* __restrict__ abp,
    const float* __restrict__ fwp, const float* __restrict__ fbp,
    const float* __restrict__ x,   float* __restrict__ outv)
{
    extern __shared__ __align__(16) char sm[];
    char* AHI = sm + OFF_AHI;
    char* ALO = sm + OFF_ALO;
    char* GRZ = sm + OFF_GRZ;
    char* GX  = sm + OFF_GX;
    char* GH  = sm + OFF_GH;
    float* hS   = (float*)(sm + OFF_HS);
    float* bias = (float*)(sm + OFF_B);
    float* gwS = (float*)(sm + OFF_EXT);
    float* gbS = (float*)(sm + OFF_EXT + 4096);
    float* ctx = (float*)(sm + OFF_EXT);
    float* mS  = (float*)(sm + OFF_EXT + 20480);
    float* ZS  = (float*)(sm + OFF_EXT + 20480 + 320);
    float* awS = (float*)(sm + OFF_EXT + 21120);
    float* fwS = (float*)(sm + OFF_EXT + 21376);
    float* scS = (float*)(sm + OFF_EXT + 21632);

    int tid = threadIdx.x, wid = tid >> 5, lid = tid & 31;
    int g = lid >> 2, tg = lid & 3;
    int node0 = blockIdx.x * MB;

    if (tid < 128) bias[tid] = bih[tid] + bhh[tid];
    else if (tid < 192) bias[tid] = bih[tid];
    else if (tid < 256) bias[tid] = bhh[tid - 64];

    if (L == 0) {
        for (int i = tid; i < FIN * HH; i += 384) gwS[i] = gwp[i];
        if (tid < 64) gbS[tid] = gbp[tid];
    } else {
        for (int i = tid; i < MB * 64; i += 384) ctx[i] = 0.0f;
        if (tid < MB) { mS[tid] = -3.0e38f; ZS[tid] = 0.0f; }
        if (tid < 64) { awS[tid] = awp[tid]; fwS[tid] = fwp[tid]; }
        if (tid == 0) scS[0] = abp[0];
    }

    {
        uint4 z = make_uint4(0, 0, 0, 0);
        for (int i = tid; i < 2560; i += 384) {
            ((uint4*)AHI)[i] = z;
            ((uint4*)ALO)[i] = z;
        }
        for (int i = tid; i < MB * 64; i += 384) hS[i] = 0.0f;
    }

    bool is_rz = wid < 8;
    int role = is_rz ? 0 : (wid < 10 ? 1 : 2);

    // persistent B fragments (hi/lo)
    u32 bh[32], bl[32];
#pragma unroll
    for (int f = 0; f < 16; f++) {
        int kk = is_rz ? (f >> 1) : (f >> 2);
        int nt = is_rz ? (f & 1)  : (f & 3);
        int nrow;
        if (role == 0)      nrow = wid * 16 + nt * 8 + g;
        else if (role == 1) nrow = 128 + (wid - 8) * 32 + nt * 8 + g;
        else                nrow = 128 + (wid - 10) * 32 + nt * 8 + g;
#pragma unroll
        for (int r = 0; r < 2; r++) {
            int k = kk * 16 + tg * 2 + r * 8;
            float w0, w1;
            if (role == 0) {
                if (k < 64) { w0 = wih[nrow * 64 + k];      w1 = wih[nrow * 64 + k + 1]; }
                else        { w0 = whh[nrow * 64 + k - 64]; w1 = whh[nrow * 64 + k - 63]; }
            } else if (role == 1) {
                w0 = wih[nrow * 64 + k]; w1 = wih[nrow * 64 + k + 1];
            } else {
                w0 = whh[nrow * 64 + k]; w1 = whh[nrow * 64 + k + 1];
            }
            __nv_bfloat16 h0, l0, h1, l1;
            split_bf16(w0, h0, l0);
            split_bf16(w1, h1, l1);
            bh[2 * f + r] = pack2(h0, h1);
            bl[2 * f + r] = pack2(l0, l1);
        }
    }

    int aoff = (role == 2) ? 128 : 0;
    int quad = lid >> 3;
    int rloc = (lid & 7) + ((quad & 1) << 3);
    int kbyte = (quad >> 1) << 4;
    int swrow = (rloc & 7) << 4;
    u32 AHI_s = (u32)__cvta_generic_to_shared(AHI);
    u32 ALO_s = (u32)__cvta_generic_to_shared(ALO);

    const uint4* in16 = reinterpret_cast<const uint4*>(g_ha2);
    float aw0 = 0.f, aw1 = 0.f, ab = 0.f;
    __syncthreads();
    if (L == 1) { aw0 = awS[2 * lid]; aw1 = awS[2 * lid + 1]; ab = scS[0]; }

    for (int t = 0; t < TT; t++) {
        // ---- stage X(t) into A tile (bf16 hi/lo, swizzled) ----
        if (L == 0) {
            for (int i = tid; i < MB * 16; i += 384) {
                int m = i >> 4, j = i & 15;
                const float4* ar = reinterpret_cast<const float4*>(
                    &g_agg[(((size_t)(node0 + m)) * TT + t) * 16]);
                float4 a0 = ar[0], a1 = ar[1], a2 = ar[2], a3 = ar[3];
                float s0 = gbS[4 * j], s1 = gbS[4 * j + 1], s2 = gbS[4 * j + 2], s3 = gbS[4 * j + 3];
#pragma unroll
                for (int f = 0; f < 16; f++) {
                    float av;
                    if (f < 4) av = ((const float*)&a0)[f];
                    else if (f < 8) av = ((const float*)&a1)[f - 4];
                    else if (f < 12) av = ((const float*)&a2)[f - 8];
                    else av = ((const float*)&a3)[f - 12];
                    const float4 wv = reinterpret_cast<const float4*>(gwS)[f * 16 + j];
                    s0 = fmaf(av, wv.x, s0);
                    s1 = fmaf(av, wv.y, s1);
                    s2 = fmaf(av, wv.z, s2);
                    s3 = fmaf(av, wv.w, s3);
                }
                s0 = fmaxf(s0, 0.f); s1 = fmaxf(s1, 0.f);
                s2 = fmaxf(s2, 0.f); s3 = fmaxf(s3, 0.f);
                __nv_bfloat16 e0, f0, e1, f1, e2, f2, e3, f3;
                split_bf16(s0, e0, f0); split_bf16(s1, e1, f1);
                split_bf16(s2, e2, f2); split_bf16(s3, e3, f3);
                uint2 phv; phv.x = pack2(e0, e1); phv.y = pack2(e2, e3);
                uint2 plv; plv.x = pack2(f0, f1); plv.y = pack2(f2, f3);
                int byt = m * 256 + ((8 * j) ^ ((m & 7) << 4));
                *(uint2*)(AHI + byt) = phv;
                *(uint2*)(ALO + byt) = plv;
            }
        } else {
            // raw copy of pre-split h1: uint4 = {hi_p, lo_p, hi_p1, lo_p1}
            for (int i = tid; i < MB * 16; i += 384) {
                int m = i >> 4, j = i & 15;
                uint4 v = in16[((size_t)(node0 + m) * TT + t) * 16 + j];
                int byt = m * 256 + ((8 * j) ^ ((m & 7) << 4));
                *(uint2*)(AHI + byt) = make_uint2(v.x, v.z);
                *(uint2*)(ALO + byt) = make_uint2(v.y, v.w);
            }
        }
        __syncthreads();

        // ---- MMA: 5 m-tiles of 16 rows ----
        for (int m = 0; m < 5; m++) {
            float acc[16];
            u32 rowb = (u32)((m * 16 + rloc) * 256 + aoff);
            if (is_rz) mma_m_tile2<8, 2>(AHI_s + rowb, kbyte, swrow, bh, bl, acc);
            else       mma_m_tile3<4, 4>(AHI_s + rowb, ALO_s + rowb, kbyte, swrow, bh, bl, acc);

            int row0 = m * 16 + g;
            int swG = g << 5;
            if (role == 0) {
#pragma unroll
                for (int nt = 0; nt < 2; nt++) {
                    int b = (4 * (wid * 16 + nt * 8 + tg * 2)) ^ swG;
                    *(float2*)(GRZ + row0 * 512 + b)       = make_float2(acc[nt * 4 + 0], acc[nt * 4 + 1]);
                    *(float2*)(GRZ + (row0 + 8) * 512 + b) = make_float2(acc[nt * 4 + 2], acc[nt * 4 + 3]);
                }
            } else {
                char* Gp = (role == 1) ? GX : GH;
                int wb = (role == 1) ? (wid - 8) : (wid - 10);
#pragma unroll
                for (int nt = 0; nt < 4; nt++) {
                    int b = (4 * (wb * 32 + nt * 8 + tg * 2)) ^ swG;
                    *(float2*)(Gp + row0 * 256 + b)       = make_float2(acc[nt * 4 + 0], acc[nt * 4 + 1]);
                    *(float2*)(Gp + (row0 + 8) * 256 + b) = make_float2(acc[nt * 4 + 2], acc[nt * 4 + 3]);
                }
            }
        }
        __syncthreads();

        // ---- gates (+ L1: online-softmax attention) ----
        for (int p = tid; p < MB * 32; p += 384) {
            int row = p >> 5, jp = p & 31;
            int sw = (row & 7) << 5;
            int o = (8 * jp) ^ sw;
            float2 rv = *(float2*)(GRZ + row * 512 + o);
            float2 zv = *(float2*)(GRZ + row * 512 + 256 + o);
            float2 xv = *(float2*)(GX + row * 256 + o);
            float2 hv = *(float2*)(GH + row * 256 + o);
            int i0 = 2 * jp;
            float hp0 = hS[row * 64 + i0], hp1 = hS[row * 64 + i0 + 1];
            float r0 = sigmoid_fast(rv.x + bias[i0]);
            float r1 = sigmoid_fast(rv.y + bias[i0 + 1]);
            float z0 = sigmoid_fast(zv.x + bias[64 + i0]);
            float z1 = sigmoid_fast(zv.y + bias[64 + i0 + 1]);
            float n0 = tanh_fast(xv.x + bias[128 + i0]     + r0 * (hv.x + bias[192 + i0]));
            float n1 = tanh_fast(xv.y + bias[128 + i0 + 1] + r1 * (hv.y + bias[192 + i0 + 1]));
            float o0 = fmaf(z0, hp0 - n0, n0);
            float o1 = fmaf(z1, hp1 - n1, n1);
            hS[row * 64 + i0] = o0;
            hS[row * 64 + i0 + 1] = o1;
            __nv_bfloat16 e0, f0, e1, f1;
            split_bf16(o0, e0, f0);
            split_bf16(o1, e1, f1);
            u32 hip = pack2(e0, e1), lop = pack2(f0, f1);
            int ba = row * 256 + 128 + ((4 * jp) ^ ((row & 7) << 4));
            *(u32*)(AHI + ba) = hip;
            *(u32*)(ALO + ba) = lop;
            if (L == 0) {
                g_ha2[((size_t)(node0 + row) * TT + t) * 32 + jp] = make_uint2(hip, lop);
            } else {
                float sc = o0 * aw0 + o1 * aw1;
#pragma unroll
                for (int of = 16; of > 0; of >>= 1) sc += __shfl_xor_sync(0xffffffffu, sc, of);
                sc += ab;
                float m_old = mS[row];
                float mn = fmaxf(m_old, sc);
                float ea = __expf(m_old - mn);
                float eb = __expf(sc - mn);
                ctx[row * 64 + i0]     = ctx[row * 64 + i0]     * ea + eb * o0;
                ctx[row * 64 + i0 + 1] = ctx[row * 64 + i0 + 1] * ea + eb * o1;
                if (jp == 0) { mS[row] = mn; ZS[row] = ZS[row] * ea + eb; }
            }
        }
        __syncthreads();
    }

    if (L == 1) {
        float fw0 = fwS[2 * lid], fw1 = fwS[2 * lid + 1];
        for (int row = wid; row < MB; row += 12) {
            float v = ctx[row * 64 + 2 * lid] * fw0 + ctx[row * 64 + 2 * lid + 1] * fw1;
#pragma unroll
            for (int of = 16; of > 0; of >>= 1) v += __shfl_xor_sync(0xffffffffu, v, of);
            if (lid == 0) {
                int node = node0 + row;
                float last = x[((size_t)(TT - 1) * NN + node) * FIN];
                outv[node] = last + v / ZS[row] + fbp[0];
            }
        }
    }
}

// ---------------- launch ----------------------------------------------------
extern "C" void kernel_launch(void* const* d_in, const int* in_sizes, int n_in,
                              void* d_out, int out_size) {
    const float* x      = (const float*)d_in[0];
    const int*   ei     = (const int*)  d_in[1];
    const float* gcn_w  = (const float*)d_in[2];
    const float* gcn_b  = (const float*)d_in[3];
    const float* w_ih0  = (const float*)d_in[4];
    const float* w_hh0  = (const float*)d_in[5];
    const float* b_ih0  = (const float*)d_in[6];
    const float* b_hh0  = (const float*)d_in[7];
    const float* w_ih1  = (const float*)d_in[8];
    const float* w_hh1  = (const float*)d_in[9];
    const float* b_ih1  = (const float*)d_in[10];
    const float* b_hh1  = (const float*)d_in[11];
    const float* attn_w = (const float*)d_in[12];
    const float* attn_b = (const float*)d_in[13];
    const float* fc_w   = (const float*)d_in[14];
    const float* fc_b   = (const float*)d_in[15];
    float* out = (float*)d_out;

    cudaFuncSetAttribute(k_rec<0>, cudaFuncAttributeMaxDynamicSharedMemorySize, SMEM_L0);
    cudaFuncSetAttribute(k_rec<1>, cudaFuncAttributeMaxDynamicSharedMemorySize, SMEM_L1);

    k_deg_init<<<(NN + 255) / 256, 256>>>();
    k_deg_edge<<<(NE + 255) / 256, 256>>>(ei);
    k_agg_init<<<(NN * TT * 4 + 255) / 256, 256>>>(x);
    k_edge_agg<<<(NE * 32 + 255) / 256, 256>>>(ei, x);

    k_rec<0><<<GRID_REC, 384, SMEM_L0>>>(w_ih0, w_hh0, b_ih0, b_hh0,
                                         gcn_w, gcn_b, nullptr, nullptr, nullptr, nullptr,
                                         x, nullptr);
    k_rec<1><<<GRID_REC, 384, SMEM_L1>>>(w_ih1, w_hh1, b_ih1, b_hh1,
                                         nullptr, nullptr, attn_w, attn_b, fc_w, fc_b,
                                         x, out);
}

// round 10
// speedup vs baseline: 1.6590x; 1.0797x over previous
#include <cuda_runtime.h>
#include <cuda_bf16.h>
#include <math.h>

#define NN 10000      // nodes
#define TT 12         // seq len
#define FIN 16        // in channels
#define HH 64         // hidden
#define K3 192        // 3*H
#define NE 160000     // edges
#define NT (NN*TT)    // 120000 rows
#define MB 80         // nodes per block (10000 = 125 * 80)
#define GRID_REC 125

typedef unsigned int u32;
typedef unsigned long long u64;

// ---------------- scratch (device globals; no allocation allowed) ----------
__device__ float g_deg[NN];
__device__ float g_agg[NN * TT * FIN];
__device__ u32  g_hap[NN * TT * (HH / 2)];   // packed bf16 hi-pairs (h1)

// ---------------- helpers ----------------------------------------------------
__device__ __forceinline__ float tanh_fast(float x) {
    float y; asm("tanh.approx.f32 %0, %1;" : "=f"(y) : "f"(x)); return y;
}
__device__ __forceinline__ float sigmoid_fast(float x) {
    return fmaf(0.5f, tanh_fast(0.5f * x), 0.5f);
}
__device__ __forceinline__ u32 pack2(__nv_bfloat16 a, __nv_bfloat16 b) {
    return (u32)__bfloat16_as_ushort(a) | ((u32)__bfloat16_as_ushort(b) << 16);
}
__device__ __forceinline__ void split_bf16(float v, __nv_bfloat16& hi, __nv_bfloat16& lo) {
    hi = __float2bfloat16(v);
    lo = __float2bfloat16(v - __bfloat162float(hi));
}
__device__ __forceinline__ void mma16816(float* c, const u32* a, u32 b0, u32 b1) {
    asm volatile(
        "mma.sync.aligned.m16n8k16.row.col.f32.bf16.bf16.f32 "
        "{%0,%1,%2,%3}, {%4,%5,%6,%7}, {%8,%9}, {%0,%1,%2,%3};"
        : "+f"(c[0]), "+f"(c[1]), "+f"(c[2]), "+f"(c[3])
        : "r"(a[0]), "r"(a[1]), "r"(a[2]), "r"(a[3]), "r"(b0), "r"(b1));
}
__device__ __forceinline__ void ldm4(u32* r, u32 saddr) {
    asm volatile("ldmatrix.sync.aligned.m8n8.x4.shared.b16 {%0,%1,%2,%3}, [%4];"
                 : "=r"(r[0]), "=r"(r[1]), "=r"(r[2]), "=r"(r[3]) : "r"(saddr));
}

// ---------------- degree / prep --------------------------------------------
__global__ void k_deg_init() {
    int i = blockIdx.x * blockDim.x + threadIdx.x;
    if (i < NN) g_deg[i] = 1.0f;
}
__global__ void k_deg_edge(const int* __restrict__ ei) {
    int e = blockIdx.x * blockDim.x + threadIdx.x;
    if (e < NE) atomicAdd(&g_deg[ei[NE + e]], 1.0f);
}
__global__ void k_agg_init(const float* __restrict__ x) {
    int idx = blockIdx.x * blockDim.x + threadIdx.x;
    if (idx >= NN * TT * 4) return;
    int n = idx / (TT * 4);
    int r = idx - n * (TT * 4);
    int t = r >> 2, f4 = r & 3;
    float di = rsqrtf(g_deg[n]);
    float c = di * di;
    float4 v = reinterpret_cast<const float4*>(x)[((size_t)t * NN + n) * 4 + f4];
    v.x *= c; v.y *= c; v.z *= c; v.w *= c;
    reinterpret_cast<float4*>(g_agg)[idx] = v;
}
__global__ void k_edge_agg(const int* __restrict__ ei, const float* __restrict__ x) {
    int gt = blockIdx.x * blockDim.x + threadIdx.x;
    int e = gt >> 5, lane = gt & 31;
    if (e >= NE) return;
    int s = ei[e];
    int d = ei[NE + e];
    float c = rsqrtf(g_deg[s]) * rsqrtf(g_deg[d]);
    const float4* x4 = reinterpret_cast<const float4*>(x);
    float4* dst4 = reinterpret_cast<float4*>(&g_agg[(size_t)d * (TT * FIN)]);
#pragma unroll
    for (int g = lane; g < 48; g += 32) {
        int t = g >> 2, f4 = g & 3;
        float4 v = x4[((size_t)t * NN + s) * 4 + f4];
        asm volatile("red.global.add.v4.f32 [%0], {%1, %2, %3, %4};"
                     :: "l"(dst4 + g), "f"(v.x * c), "f"(v.y * c), "f"(v.z * c), "f"(v.w * c)
                     : "memory");
    }
}

// ---------------- fused HMMA GRU layers --------------------------------------
// All gates 2-term (x_hi*w_hi + x_hi*w_lo): activation-lo operand eliminated.
// Every warp now issues 160 K16-MMA units per timestep (balanced).
// Loop: 2 barriers/timestep; X(t+1) staged during gates(t).
#define OFF_AHI 0              // bf16 A tile [80 rows x 256B]: X half | H half
#define OFF_GRZ 20480          // fp32 [80][128], swizzled
#define OFF_GX  61440          // fp32 [80][64]
#define OFF_GH  81920
#define OFF_HS  102400         // fp32 h state [80][64]
#define OFF_B   122880         // biases: 256 floats
#define OFF_EXT 123904
#define SMEM_L0 (OFF_EXT + 4096 + 256)
#define SMEM_L1 (OFF_EXT + 20480 + 640 + 256 + 256 + 16)

// 2-term m-tile: acc = a_hi*b_hi + a_hi*b_lo (two independent chains)
template<int KKS, int NTS>
__device__ __forceinline__ void mma_m_tile2(
    u32 ahi_base, int kbyte, int swrow,
    const u32* bh, const u32* bl, float* acc)
{
    float hh[NTS * 4], hl[NTS * 4];
#pragma unroll
    for (int q = 0; q < NTS * 4; q++) { hh[q] = 0.f; hl[q] = 0.f; }
#pragma unroll
    for (int kk = 0; kk < KKS; kk++) {
        u32 off = (u32)((kk * 32 + kbyte) ^ swrow);
        u32 ah[4];
        ldm4(ah, ahi_base + off);
#pragma unroll
        for (int nt = 0; nt < NTS; nt++) {
            int f = kk * NTS + nt;
            mma16816(hh + nt * 4, ah, bh[2 * f], bh[2 * f + 1]);
            mma16816(hl + nt * 4, ah, bl[2 * f], bl[2 * f + 1]);
        }
    }
#pragma unroll
    for (int q = 0; q < NTS * 4; q++) acc[q] = hh[q] + hl[q];
}

template<int L>
__global__ __launch_bounds__(384, 1) void k_rec(
    const float* __restrict__ wih, const float* __restrict__ whh,
    const float* __restrict__ bih, const float* __restrict__ bhh,
    const float* __restrict__ gwp, const float* __restrict__ gbp,
    const float* __restrict__ awp, const float* __restrict__ abp,
    const float* __restrict__ fwp, const float* __restrict__ fbp,
    const float* __restrict__ x,   float* __restrict__ outv)
{
    extern __shared__ __align__(16) char sm[];
    char* AHI = sm + OFF_AHI;
    char* GRZ = sm + OFF_GRZ;
    char* GX  = sm + OFF_GX;
    char* GH  = sm + OFF_GH;
    float* hS   = (float*)(sm + OFF_HS);
    float* bias = (float*)(sm + OFF_B);
    float* gwS = (float*)(sm + OFF_EXT);
    float* gbS = (float*)(sm + OFF_EXT + 4096);
    float* ctx = (float*)(sm + OFF_EXT);
    float* mS  = (float*)(sm + OFF_EXT + 20480);
    float* ZS  = (float*)(sm + OFF_EXT + 20480 + 320);
    float* awS = (float*)(sm + OFF_EXT + 21120);
    float* fwS = (float*)(sm + OFF_EXT + 21376);
    float* scS = (float*)(sm + OFF_EXT + 21632);

    int tid = threadIdx.x, wid = tid >> 5, lid = tid & 31;
    int g = lid >> 2, tg = lid & 3;
    int node0 = blockIdx.x * MB;

    if (tid < 128) bias[tid] = bih[tid] + bhh[tid];
    else if (tid < 192) bias[tid] = bih[tid];
    else if (tid < 256) bias[tid] = bhh[tid - 64];

    if (L == 0) {
        for (int i = tid; i < FIN * HH; i += 384) gwS[i] = gwp[i];
        if (tid < 64) gbS[tid] = gbp[tid];
    } else {
        for (int i = tid; i < MB * 64; i += 384) ctx[i] = 0.0f;
        if (tid < MB) { mS[tid] = -3.0e38f; ZS[tid] = 0.0f; }
        if (tid < 64) { awS[tid] = awp[tid]; fwS[tid] = fwp[tid]; }
        if (tid == 0) scS[0] = abp[0];
    }

    {
        uint4 z = make_uint4(0, 0, 0, 0);
        for (int i = tid; i < 1280; i += 384) ((uint4*)AHI)[i] = z;
        for (int i = tid; i < MB * 64; i += 384) hS[i] = 0.0f;
    }

    bool is_rz = wid < 8;
    int role = is_rz ? 0 : (wid < 10 ? 1 : 2);

    // persistent B fragments (w_hi / w_lo)
    u32 bh[32], bl[32];
#pragma unroll
    for (int f = 0; f < 16; f++) {
        int kk = is_rz ? (f >> 1) : (f >> 2);
        int nt = is_rz ? (f & 1)  : (f & 3);
        int nrow;
        if (role == 0)      nrow = wid * 16 + nt * 8 + g;
        else if (role == 1) nrow = 128 + (wid - 8) * 32 + nt * 8 + g;
        else                nrow = 128 + (wid - 10) * 32 + nt * 8 + g;
#pragma unroll
        for (int r = 0; r < 2; r++) {
            int k = kk * 16 + tg * 2 + r * 8;
            float w0, w1;
            if (role == 0) {
                if (k < 64) { w0 = wih[nrow * 64 + k];      w1 = wih[nrow * 64 + k + 1]; }
                else        { w0 = whh[nrow * 64 + k - 64]; w1 = whh[nrow * 64 + k - 63]; }
            } else if (role == 1) {
                w0 = wih[nrow * 64 + k]; w1 = wih[nrow * 64 + k + 1];
            } else {
                w0 = whh[nrow * 64 + k]; w1 = whh[nrow * 64 + k + 1];
            }
            __nv_bfloat16 h0, l0, h1, l1;
            split_bf16(w0, h0, l0);
            split_bf16(w1, h1, l1);
            bh[2 * f + r] = pack2(h0, h1);
            bl[2 * f + r] = pack2(l0, l1);
        }
    }

    int aoff = (role == 2) ? 128 : 0;
    int quad = lid >> 3;
    int rloc = (lid & 7) + ((quad & 1) << 3);
    int kbyte = (quad >> 1) << 4;
    int swrow = (rloc & 7) << 4;
    u32 AHI_s = (u32)__cvta_generic_to_shared(AHI);

    float aw0 = 0.f, aw1 = 0.f, ab = 0.f;
    __syncthreads();
    if (L == 1) { aw0 = awS[2 * lid]; aw1 = awS[2 * lid + 1]; ab = scS[0]; }

    // stage X(tt) into the X half of the A tile (bf16 hi only, swizzled)
    auto stage_x = [&](int tt) {
        if (L == 0) {
            for (int i = tid; i < MB * 16; i += 384) {
                int m = i >> 4, j = i & 15;
                const float4* ar = reinterpret_cast<const float4*>(
                    &g_agg[(((size_t)(node0 + m)) * TT + tt) * 16]);
                float4 a0 = ar[0], a1 = ar[1], a2 = ar[2], a3 = ar[3];
                float s0 = gbS[4 * j], s1 = gbS[4 * j + 1], s2 = gbS[4 * j + 2], s3 = gbS[4 * j + 3];
#pragma unroll
                for (int f = 0; f < 16; f++) {
                    float av;
                    if (f < 4) av = ((const float*)&a0)[f];
                    else if (f < 8) av = ((const float*)&a1)[f - 4];
                    else if (f < 12) av = ((const float*)&a2)[f - 8];
                    else av = ((const float*)&a3)[f - 12];
                    const float4 wv = reinterpret_cast<const float4*>(gwS)[f * 16 + j];
                    s0 = fmaf(av, wv.x, s0);
                    s1 = fmaf(av, wv.y, s1);
                    s2 = fmaf(av, wv.z, s2);
                    s3 = fmaf(av, wv.w, s3);
                }
                s0 = fmaxf(s0, 0.f); s1 = fmaxf(s1, 0.f);
                s2 = fmaxf(s2, 0.f); s3 = fmaxf(s3, 0.f);
                uint2 phv;
                phv.x = pack2(__float2bfloat16(s0), __float2bfloat16(s1));
                phv.y = pack2(__float2bfloat16(s2), __float2bfloat16(s3));
                int byt = m * 256 + ((8 * j) ^ ((m & 7) << 4));
                *(uint2*)(AHI + byt) = phv;
            }
        } else {
            const uint2* in8 = reinterpret_cast<const uint2*>(g_hap);
            for (int i = tid; i < MB * 16; i += 384) {
                int m = i >> 4, j = i & 15;
                uint2 v = in8[((size_t)(node0 + m) * TT + tt) * 16 + j];
                int byt = m * 256 + ((8 * j) ^ ((m & 7) << 4));
                *(uint2*)(AHI + byt) = v;
            }
        }
    };

    stage_x(0);
    __syncthreads();

    for (int t = 0; t < TT; t++) {
        // ---- MMA: 5 m-tiles of 16 rows ----
        for (int m = 0; m < 5; m++) {
            float acc[16];
            u32 rowb = (u32)((m * 16 + rloc) * 256 + aoff);
            if (is_rz) mma_m_tile2<8, 2>(AHI_s + rowb, kbyte, swrow, bh, bl, acc);
            else       mma_m_tile2<4, 4>(AHI_s + rowb, kbyte, swrow, bh, bl, acc);

            int row0 = m * 16 + g;
            int swG = g << 5;
            if (role == 0) {
#pragma unroll
                for (int nt = 0; nt < 2; nt++) {
                    int b = (4 * (wid * 16 + nt * 8 + tg * 2)) ^ swG;
                    *(float2*)(GRZ + row0 * 512 + b)       = make_float2(acc[nt * 4 + 0], acc[nt * 4 + 1]);
                    *(float2*)(GRZ + (row0 + 8) * 512 + b) = make_float2(acc[nt * 4 + 2], acc[nt * 4 + 3]);
                }
            } else {
                char* Gp = (role == 1) ? GX : GH;
                int wb = (role == 1) ? (wid - 8) : (wid - 10);
#pragma unroll
                for (int nt = 0; nt < 4; nt++) {
                    int b = (4 * (wb * 32 + nt * 8 + tg * 2)) ^ swG;
                    *(float2*)(Gp + row0 * 256 + b)       = make_float2(acc[nt * 4 + 0], acc[nt * 4 + 1]);
                    *(float2*)(Gp + (row0 + 8) * 256 + b) = make_float2(acc[nt * 4 + 2], acc[nt * 4 + 3]);
                }
            }
        }
        __syncthreads();

        // ---- gates (+ L1: online-softmax attention) ----
        for (int p = tid; p < MB * 32; p += 384) {
            int row = p >> 5, jp = p & 31;
            int sw = (row & 7) << 5;
            int o = (8 * jp) ^ sw;
            float2 rv = *(float2*)(GRZ + row * 512 + o);
            float2 zv = *(float2*)(GRZ + row * 512 + 256 + o);
            float2 xv = *(float2*)(GX + row * 256 + o);
            float2 hv = *(float2*)(GH + row * 256 + o);
            int i0 = 2 * jp;
            float hp0 = hS[row * 64 + i0], hp1 = hS[row * 64 + i0 + 1];
            float r0 = sigmoid_fast(rv.x + bias[i0]);
            float r1 = sigmoid_fast(rv.y + bias[i0 + 1]);
            float z0 = sigmoid_fast(zv.x + bias[64 + i0]);
            float z1 = sigmoid_fast(zv.y + bias[64 + i0 + 1]);
            float n0 = tanh_fast(xv.x + bias[128 + i0]     + r0 * (hv.x + bias[192 + i0]));
            float n1 = tanh_fast(xv.y + bias[128 + i0 + 1] + r1 * (hv.y + bias[192 + i0 + 1]));
            float o0 = fmaf(z0, hp0 - n0, n0);
            float o1 = fmaf(z1, hp1 - n1, n1);
            hS[row * 64 + i0] = o0;
            hS[row * 64 + i0 + 1] = o1;
            u32 hip = pack2(__float2bfloat16(o0), __float2bfloat16(o1));
            int ba = row * 256 + 128 + ((4 * jp) ^ ((row & 7) << 4));
            *(u32*)(AHI + ba) = hip;
            if (L == 0) {
                g_hap[((size_t)(node0 + row) * TT + t) * 32 + jp] = hip;
            } else {
                float sc = o0 * aw0 + o1 * aw1;
#pragma unroll
                for (int of = 16; of > 0; of >>= 1) sc += __shfl_xor_sync(0xffffffffu, sc, of);
                sc += ab;
                float m_old = mS[row];
                float mn = fmaxf(m_old, sc);
                float ea = __expf(m_old - mn);
                float eb = __expf(sc - mn);
                ctx[row * 64 + i0]     = ctx[row * 64 + i0]     * ea + eb * o0;
                ctx[row * 64 + i0 + 1] = ctx[row * 64 + i0 + 1] * ea + eb * o1;
                if (jp == 0) { mS[row] = mn; ZS[row] = ZS[row] * ea + eb; }
            }
        }
        // ---- overlap: stage next timestep's X while gates warps drain ----
        if (t + 1 < TT) stage_x(t + 1);
        __syncthreads();
    }

    if (L == 1) {
        float fw0 = fwS[2 * lid], fw1 = fwS[2 * lid + 1];
        for (int row = wid; row < MB; row += 12) {
            float v = ctx[row * 64 + 2 * lid] * fw0 + ctx[row * 64 + 2 * lid + 1] * fw1;
#pragma unroll
            for (int of = 16; of > 0; of >>= 1) v += __shfl_xor_sync(0xffffffffu, v, of);
            if (lid == 0) {
                int node = node0 + row;
                float last = x[((size_t)(TT - 1) * NN + node) * FIN];
                outv[node] = last + v / ZS[row] + fbp[0];
            }
        }
    }
}

// ---------------- launch ----------------------------------------------------
extern "C" void kernel_launch(void* const* d_in, const int* in_sizes, int n_in,
                              void* d_out, int out_size) {
    const float* x      = (const float*)d_in[0];
    const int*   ei     = (const int*)  d_in[1];
    const float* gcn_w  = (const float*)d_in[2];
    const float* gcn_b  = (const float*)d_in[3];
    const float* w_ih0  = (const float*)d_in[4];
    const float* w_hh0  = (const float*)d_in[5];
    const float* b_ih0  = (const float*)d_in[6];
    const float* b_hh0  = (const float*)d_in[7];
    const float* w_ih1  = (const float*)d_in[8];
    const float* w_hh1  = (const float*)d_in[9];
    const float* b_ih1  = (const float*)d_in[10];
    const float* b_hh1  = (const float*)d_in[11];
    const float* attn_w = (const float*)d_in[12];
    const float* attn_b = (const float*)d_in[13];
    const float* fc_w   = (const float*)d_in[14];
    const float* fc_b   = (const float*)d_in[15];
    float* out = (float*)d_out;

    cudaFuncSetAttribute(k_rec<0>, cudaFuncAttributeMaxDynamicSharedMemorySize, SMEM_L0);
    cudaFuncSetAttribute(k_rec<1>, cudaFuncAttributeMaxDynamicSharedMemorySize, SMEM_L1);

    k_deg_init<<<(NN + 255) / 256, 256>>>();
    k_deg_edge<<<(NE + 255) / 256, 256>>>(ei);
    k_agg_init<<<(NN * TT * 4 + 255) / 256, 256>>>(x);
    k_edge_agg<<<(NE * 32 + 255) / 256, 256>>>(ei, x);

    k_rec<0><<<GRID_REC, 384, SMEM_L0>>>(w_ih0, w_hh0, b_ih0, b_hh0,
                                         gcn_w, gcn_b, nullptr, nullptr, nullptr, nullptr,
                                         x, nullptr);
    k_rec<1><<<GRID_REC, 384, SMEM_L1>>>(w_ih1, w_hh1, b_ih1, b_hh1,
                                         nullptr, nullptr, attn_w, attn_b, fc_w, fc_b,
                                         x, out);
}

// round 11
// speedup vs baseline: 1.7294x; 1.0424x over previous
#include <cuda_runtime.h>
#include <cuda_bf16.h>
#include <math.h>

#define NN 10000      // nodes
#define TT 12         // seq len
#define FIN 16        // in channels
#define HH 64         // hidden
#define K3 192        // 3*H
#define NE 160000     // edges
#define NT (NN*TT)    // 120000 rows
#define MB 80         // nodes per block (10000 = 125 * 80)
#define GRID_REC 125
#define NTH 768       // 24 warps: 2 K-halves x 12 N-role warps

typedef unsigned int u32;
typedef unsigned long long u64;

// ---------------- scratch (device globals; no allocation allowed) ----------
__device__ float g_deg[NN];
__device__ float g_agg[NN * TT * FIN];
__device__ u32  g_hap[NN * TT * (HH / 2)];   // packed bf16 hi-pairs (h1)

// ---------------- helpers ----------------------------------------------------
__device__ __forceinline__ float tanh_fast(float x) {
    float y; asm("tanh.approx.f32 %0, %1;" : "=f"(y) : "f"(x)); return y;
}
__device__ __forceinline__ float sigmoid_fast(float x) {
    return fmaf(0.5f, tanh_fast(0.5f * x), 0.5f);
}
__device__ __forceinline__ u32 pack2(__nv_bfloat16 a, __nv_bfloat16 b) {
    return (u32)__bfloat16_as_ushort(a) | ((u32)__bfloat16_as_ushort(b) << 16);
}
__device__ __forceinline__ void split_bf16(float v, __nv_bfloat16& hi, __nv_bfloat16& lo) {
    hi = __float2bfloat16(v);
    lo = __float2bfloat16(v - __bfloat162float(hi));
}
__device__ __forceinline__ void mma16816(float* c, const u32* a, u32 b0, u32 b1) {
    asm volatile(
        "mma.sync.aligned.m16n8k16.row.col.f32.bf16.bf16.f32 "
        "{%0,%1,%2,%3}, {%4,%5,%6,%7}, {%8,%9}, {%0,%1,%2,%3};"
        : "+f"(c[0]), "+f"(c[1]), "+f"(c[2]), "+f"(c[3])
        : "r"(a[0]), "r"(a[1]), "r"(a[2]), "r"(a[3]), "r"(b0), "r"(b1));
}
__device__ __forceinline__ void ldm4(u32* r, u32 saddr) {
    asm volatile("ldmatrix.sync.aligned.m8n8.x4.shared.b16 {%0,%1,%2,%3}, [%4];"
                 : "=r"(r[0]), "=r"(r[1]), "=r"(r[2]), "=r"(r[3]) : "r"(saddr));
}

// ---------------- degree / prep --------------------------------------------
__global__ void k_deg_init() {
    int i = blockIdx.x * blockDim.x + threadIdx.x;
    if (i < NN) g_deg[i] = 1.0f;
}
__global__ void k_deg_edge(const int* __restrict__ ei) {
    int e = blockIdx.x * blockDim.x + threadIdx.x;
    if (e < NE) atomicAdd(&g_deg[ei[NE + e]], 1.0f);
}
__global__ void k_agg_init(const float* __restrict__ x) {
    int idx = blockIdx.x * blockDim.x + threadIdx.x;
    if (idx >= NN * TT * 4) return;
    int n = idx / (TT * 4);
    int r = idx - n * (TT * 4);
    int t = r >> 2, f4 = r & 3;
    float di = rsqrtf(g_deg[n]);
    float c = di * di;
    float4 v = reinterpret_cast<const float4*>(x)[((size_t)t * NN + n) * 4 + f4];
    v.x *= c; v.y *= c; v.z *= c; v.w *= c;
    reinterpret_cast<float4*>(g_agg)[idx] = v;
}
__global__ void k_edge_agg(const int* __restrict__ ei, const float* __restrict__ x) {
    int gt = blockIdx.x * blockDim.x + threadIdx.x;
    int e = gt >> 5, lane = gt & 31;
    if (e >= NE) return;
    int s = ei[e];
    int d = ei[NE + e];
    float c = rsqrtf(g_deg[s]) * rsqrtf(g_deg[d]);
    const float4* x4 = reinterpret_cast<const float4*>(x);
    float4* dst4 = reinterpret_cast<float4*>(&g_agg[(size_t)d * (TT * FIN)]);
#pragma unroll
    for (int g = lane; g < 48; g += 32) {
        int t = g >> 2, f4 = g & 3;
        float4 v = x4[((size_t)t * NN + s) * 4 + f4];
        asm volatile("red.global.add.v4.f32 [%0], {%1, %2, %3, %4};"
                     :: "l"(dst4 + g), "f"(v.x * c), "f"(v.y * c), "f"(v.z * c), "f"(v.w * c)
                     : "memory");
    }
}

// ---------------- fused HMMA GRU layers --------------------------------------
// 24 warps = 2 K-halves x {8 rz + 2 xn + 2 hn}. Each warp: 32 weight regs,
// 16 MMA per m-tile, partial fp32 sums into per-half G buffers; gates add.
#define OFF_AHI  0               // bf16 A tile [80 x 256B]: X half | H half
#define OFF_GRZ0 20480           // fp32 [80][128] swizzled, K-half 0
#define OFF_GRZ1 61440           // K-half 1
#define OFF_GX0  102400          // fp32 [80][64]
#define OFF_GX1  122880
#define OFF_GH0  143360
#define OFF_GH1  163840
#define OFF_HS   184320          // fp32 h state [80][64]
#define OFF_B    204800          // biases: 256 floats
#define OFF_EXT  205824
#define SMEM_L0 (OFF_EXT + 4096 + 256)
#define SMEM_L1 (OFF_EXT + 20480 + 640 + 256 + 256 + 16)

// single-acc 2-term m-tile: acc += a_hi*(b_hi + b_lo products)
template<int KKS, int NTS>
__device__ __forceinline__ void mma_m_tile(
    u32 a_base, int kbyte, int swrow, int kk0,
    const u32* bh, const u32* bl, float* acc)
{
#pragma unroll
    for (int q = 0; q < NTS * 4; q++) acc[q] = 0.f;
#pragma unroll
    for (int kk = 0; kk < KKS; kk++) {
        u32 off = (u32)((((kk + kk0) * 32) + kbyte) ^ swrow);
        u32 ah[4];
        ldm4(ah, a_base + off);
#pragma unroll
        for (int nt = 0; nt < NTS; nt++) {
            int f = kk * NTS + nt;
            mma16816(acc + nt * 4, ah, bh[2 * f], bh[2 * f + 1]);
            mma16816(acc + nt * 4, ah, bl[2 * f], bl[2 * f + 1]);
        }
    }
}

template<int L>
__global__ __launch_bounds__(NTH, 1) void k_rec(
    const float* __restrict__ wih, const float* __restrict__ whh,
    const float* __restrict__ bih, const float* __restrict__ bhh,
    const float* __restrict__ gwp, const float* __restrict__ gbp,
    const float* __restrict__ awp, const float* __restrict__ abp,
    const float* __restrict__ fwp, const float* __restrict__ fbp,
    const float* __restrict__ x,   float* __restrict__ outv)
{
    extern __shared__ __align__(16) char sm[];
    char* AHI  = sm + OFF_AHI;
    char* GRZ0 = sm + OFF_GRZ0;
    char* GRZ1 = sm + OFF_GRZ1;
    char* GX0  = sm + OFF_GX0;
    char* GX1  = sm + OFF_GX1;
    char* GH0  = sm + OFF_GH0;
    char* GH1  = sm + OFF_GH1;
    float* hS   = (float*)(sm + OFF_HS);
    float* bias = (float*)(sm + OFF_B);
    float* gwS = (float*)(sm + OFF_EXT);
    float* gbS = (float*)(sm + OFF_EXT + 4096);
    float* ctx = (float*)(sm + OFF_EXT);
    float* mS  = (float*)(sm + OFF_EXT + 20480);
    float* ZS  = (float*)(sm + OFF_EXT + 20480 + 320);
    float* awS = (float*)(sm + OFF_EXT + 21120);
    float* fwS = (float*)(sm + OFF_EXT + 21376);
    float* scS = (float*)(sm + OFF_EXT + 21632);

    int tid = threadIdx.x, wid = tid >> 5, lid = tid & 31;
    int g = lid >> 2, tg = lid & 3;
    int node0 = blockIdx.x * MB;
    int wl = wid % 12;          // N-role warp index
    int half = wid / 12;        // K-half

    if (tid < 128) bias[tid] = bih[tid] + bhh[tid];
    else if (tid < 192) bias[tid] = bih[tid];
    else if (tid < 256) bias[tid] = bhh[tid - 64];

    if (L == 0) {
        for (int i = tid; i < FIN * HH; i += NTH) gwS[i] = gwp[i];
        if (tid >= 256 && tid < 320) gbS[tid - 256] = gbp[tid - 256];
    } else {
        for (int i = tid; i < MB * 64; i += NTH) ctx[i] = 0.0f;
        if (tid >= 256 && tid < 256 + MB) { mS[tid - 256] = -3.0e38f; ZS[tid - 256] = 0.0f; }
        if (tid >= 384 && tid < 448) { awS[tid - 384] = awp[tid - 384]; fwS[tid - 384] = fwp[tid - 384]; }
        if (tid == 448) scS[0] = abp[0];
    }

    {
        uint4 z = make_uint4(0, 0, 0, 0);
        for (int i = tid; i < 1280; i += NTH) ((uint4*)AHI)[i] = z;
        for (int i = tid; i < MB * 64; i += NTH) hS[i] = 0.0f;
    }

    bool is_rz = wl < 8;
    int role = is_rz ? 0 : (wl < 10 ? 1 : 2);
    int kk0 = is_rz ? half * 4 : half * 2;

    // persistent B fragments (w_hi / w_lo): 8 slots x 2 regs
    u32 bh[16], bl[16];
#pragma unroll
    for (int f = 0; f < 8; f++) {
        int kk = is_rz ? (f >> 1) : (f >> 2);
        int nt = is_rz ? (f & 1)  : (f & 3);
        int nrow;
        if (role == 0)      nrow = wl * 16 + nt * 8 + g;
        else if (role == 1) nrow = 128 + (wl - 8) * 32 + nt * 8 + g;
        else                nrow = 128 + (wl - 10) * 32 + nt * 8 + g;
#pragma unroll
        for (int r = 0; r < 2; r++) {
            int k = (kk + kk0) * 16 + tg * 2 + r * 8;
            float w0, w1;
            if (role == 0) {
                if (k < 64) { w0 = wih[nrow * 64 + k];      w1 = wih[nrow * 64 + k + 1]; }
                else        { w0 = whh[nrow * 64 + k - 64]; w1 = whh[nrow * 64 + k - 63]; }
            } else if (role == 1) {
                w0 = wih[nrow * 64 + k]; w1 = wih[nrow * 64 + k + 1];
            } else {
                w0 = whh[nrow * 64 + k]; w1 = whh[nrow * 64 + k + 1];
            }
            __nv_bfloat16 h0, l0, h1, l1;
            split_bf16(w0, h0, l0);
            split_bf16(w1, h1, l1);
            bh[2 * f + r] = pack2(h0, h1);
            bl[2 * f + r] = pack2(l0, l1);
        }
    }

    int aoff = (role == 2) ? 128 : 0;
    int quad = lid >> 3;
    int rloc = (lid & 7) + ((quad & 1) << 3);
    int kbyte = (quad >> 1) << 4;
    int swrow = (rloc & 7) << 4;
    u32 AHI_s = (u32)__cvta_generic_to_shared(AHI);

    float aw0 = 0.f, aw1 = 0.f, ab = 0.f;
    __syncthreads();
    if (L == 1) { aw0 = awS[2 * lid]; aw1 = awS[2 * lid + 1]; ab = scS[0]; }

    // stage X(tt) into the X half of the A tile (bf16 hi only, swizzled)
    auto stage_x = [&](int tt) {
        if (L == 0) {
            for (int i = tid; i < MB * 16; i += NTH) {
                int m = i >> 4, j = i & 15;
                const float4* ar = reinterpret_cast<const float4*>(
                    &g_agg[(((size_t)(node0 + m)) * TT + tt) * 16]);
                float4 a0 = ar[0], a1 = ar[1], a2 = ar[2], a3 = ar[3];
                float s0 = gbS[4 * j], s1 = gbS[4 * j + 1], s2 = gbS[4 * j + 2], s3 = gbS[4 * j + 3];
#pragma unroll
                for (int f = 0; f < 16; f++) {
                    float av;
                    if (f < 4) av = ((const float*)&a0)[f];
                    else if (f < 8) av = ((const float*)&a1)[f - 4];
                    else if (f < 12) av = ((const float*)&a2)[f - 8];
                    else av = ((const float*)&a3)[f - 12];
                    const float4 wv = reinterpret_cast<const float4*>(gwS)[f * 16 + j];
                    s0 = fmaf(av, wv.x, s0);
                    s1 = fmaf(av, wv.y, s1);
                    s2 = fmaf(av, wv.z, s2);
                    s3 = fmaf(av, wv.w, s3);
                }
                s0 = fmaxf(s0, 0.f); s1 = fmaxf(s1, 0.f);
                s2 = fmaxf(s2, 0.f); s3 = fmaxf(s3, 0.f);
                uint2 phv;
                phv.x = pack2(__float2bfloat16(s0), __float2bfloat16(s1));
                phv.y = pack2(__float2bfloat16(s2), __float2bfloat16(s3));
                int byt = m * 256 + ((8 * j) ^ ((m & 7) << 4));
                *(uint2*)(AHI + byt) = phv;
            }
        } else {
            const uint2* in8 = reinterpret_cast<const uint2*>(g_hap);
            for (int i = tid; i < MB * 16; i += NTH) {
                int m = i >> 4, j = i & 15;
                uint2 v = in8[((size_t)(node0 + m) * TT + tt) * 16 + j];
                int byt = m * 256 + ((8 * j) ^ ((m & 7) << 4));
                *(uint2*)(AHI + byt) = v;
            }
        }
    };

    stage_x(0);
    __syncthreads();

    for (int t = 0; t < TT; t++) {
        // ---- MMA: 5 m-tiles of 16 rows, each warp does its K-half ----
        for (int m = 0; m < 5; m++) {
            float acc[16];
            u32 rowb = (u32)((m * 16 + rloc) * 256 + aoff);
            if (is_rz) mma_m_tile<4, 2>(AHI_s + rowb, kbyte, swrow, kk0, bh, bl, acc);
            else       mma_m_tile<2, 4>(AHI_s + rowb, kbyte, swrow, kk0, bh, bl, acc);

            int row0 = m * 16 + g;
            int swG = g << 5;
            if (role == 0) {
                char* Gp = half ? GRZ1 : GRZ0;
#pragma unroll
                for (int nt = 0; nt < 2; nt++) {
                    int b = (4 * (wl * 16 + nt * 8 + tg * 2)) ^ swG;
                    *(float2*)(Gp + row0 * 512 + b)       = make_float2(acc[nt * 4 + 0], acc[nt * 4 + 1]);
                    *(float2*)(Gp + (row0 + 8) * 512 + b) = make_float2(acc[nt * 4 + 2], acc[nt * 4 + 3]);
                }
            } else {
                char* Gp = (role == 1) ? (half ? GX1 : GX0) : (half ? GH1 : GH0);
                int wb = (role == 1) ? (wl - 8) : (wl - 10);
#pragma unroll
                for (int nt = 0; nt < 4; nt++) {
                    int b = (4 * (wb * 32 + nt * 8 + tg * 2)) ^ swG;
                    *(float2*)(Gp + row0 * 256 + b)       = make_float2(acc[nt * 4 + 0], acc[nt * 4 + 1]);
                    *(float2*)(Gp + (row0 + 8) * 256 + b) = make_float2(acc[nt * 4 + 2], acc[nt * 4 + 3]);
                }
            }
        }
        __syncthreads();

        // ---- gates (+ L1: online-softmax attention); sum K-half partials ----
        for (int p = tid; p < MB * 32; p += NTH) {
            int row = p >> 5, jp = p & 31;
            int sw = (row & 7) << 5;
            int o = (8 * jp) ^ sw;
            float2 rva = *(float2*)(GRZ0 + row * 512 + o);
            float2 rvb = *(float2*)(GRZ1 + row * 512 + o);
            float2 zva = *(float2*)(GRZ0 + row * 512 + 256 + o);
            float2 zvb = *(float2*)(GRZ1 + row * 512 + 256 + o);
            float2 xva = *(float2*)(GX0 + row * 256 + o);
            float2 xvb = *(float2*)(GX1 + row * 256 + o);
            float2 hva = *(float2*)(GH0 + row * 256 + o);
            float2 hvb = *(float2*)(GH1 + row * 256 + o);
            float rx = rva.x + rvb.x, ry = rva.y + rvb.y;
            float zx = zva.x + zvb.x, zy = zva.y + zvb.y;
            float xx = xva.x + xvb.x, xy = xva.y + xvb.y;
            float hx = hva.x + hvb.x, hy = hva.y + hvb.y;
            int i0 = 2 * jp;
            float hp0 = hS[row * 64 + i0], hp1 = hS[row * 64 + i0 + 1];
            float r0 = sigmoid_fast(rx + bias[i0]);
            float r1 = sigmoid_fast(ry + bias[i0 + 1]);
            float z0 = sigmoid_fast(zx + bias[64 + i0]);
            float z1 = sigmoid_fast(zy + bias[64 + i0 + 1]);
            float n0 = tanh_fast(xx + bias[128 + i0]     + r0 * (hx + bias[192 + i0]));
            float n1 = tanh_fast(xy + bias[128 + i0 + 1] + r1 * (hy + bias[192 + i0 + 1]));
            float o0 = fmaf(z0, hp0 - n0, n0);
            float o1 = fmaf(z1, hp1 - n1, n1);
            hS[row * 64 + i0] = o0;
            hS[row * 64 + i0 + 1] = o1;
            u32 hip = pack2(__float2bfloat16(o0), __float2bfloat16(o1));
            int ba = row * 256 + 128 + ((4 * jp) ^ ((row & 7) << 4));
            *(u32*)(AHI + ba) = hip;
            if (L == 0) {
                g_hap[((size_t)(node0 + row) * TT + t) * 32 + jp] = hip;
            } else {
                float sc = o0 * aw0 + o1 * aw1;
#pragma unroll
                for (int of = 16; of > 0; of >>= 1) sc += __shfl_xor_sync(0xffffffffu, sc, of);
                sc += ab;
                float m_old = mS[row];
                float mn = fmaxf(m_old, sc);
                float ea = __expf(m_old - mn);
                float eb = __expf(sc - mn);
                ctx[row * 64 + i0]     = ctx[row * 64 + i0]     * ea + eb * o0;
                ctx[row * 64 + i0 + 1] = ctx[row * 64 + i0 + 1] * ea + eb * o1;
                if (jp == 0) { mS[row] = mn; ZS[row] = ZS[row] * ea + eb; }
            }
        }
        // ---- overlap: stage next timestep's X while gates warps drain ----
        if (t + 1 < TT) stage_x(t + 1);
        __syncthreads();
    }

    if (L == 1) {
        float fw0 = fwS[2 * lid], fw1 = fwS[2 * lid + 1];
        for (int row = wid; row < MB; row += 24) {
            float v = ctx[row * 64 + 2 * lid] * fw0 + ctx[row * 64 + 2 * lid + 1] * fw1;
#pragma unroll
            for (int of = 16; of > 0; of >>= 1) v += __shfl_xor_sync(0xffffffffu, v, of);
            if (lid == 0) {
                int node = node0 + row;
                float last = x[((size_t)(TT - 1) * NN + node) * FIN];
                outv[node] = last + v / ZS[row] + fbp[0];
            }
        }
    }
}

// ---------------- launch ----------------------------------------------------
extern "C" void kernel_launch(void* const* d_in, const int* in_sizes, int n_in,
                              void* d_out, int out_size) {
    const float* x      = (const float*)d_in[0];
    const int*   ei     = (const int*)  d_in[1];
    const float* gcn_w  = (const float*)d_in[2];
    const float* gcn_b  = (const float*)d_in[3];
    const float* w_ih0  = (const float*)d_in[4];
    const float* w_hh0  = (const float*)d_in[5];
    const float* b_ih0  = (const float*)d_in[6];
    const float* b_hh0  = (const float*)d_in[7];
    const float* w_ih1  = (const float*)d_in[8];
    const float* w_hh1  = (const float*)d_in[9];
    const float* b_ih1  = (const float*)d_in[10];
    const float* b_hh1  = (const float*)d_in[11];
    const float* attn_w = (const float*)d_in[12];
    const float* attn_b = (const float*)d_in[13];
    const float* fc_w   = (const float*)d_in[14];
    const float* fc_b   = (const float*)d_in[15];
    float* out = (float*)d_out;

    cudaFuncSetAttribute(k_rec<0>, cudaFuncAttributeMaxDynamicSharedMemorySize, SMEM_L0);
    cudaFuncSetAttribute(k_rec<1>, cudaFuncAttributeMaxDynamicSharedMemorySize, SMEM_L1);

    k_deg_init<<<(NN + 255) / 256, 256>>>();
    k_deg_edge<<<(NE + 255) / 256, 256>>>(ei);
    k_agg_init<<<(NN * TT * 4 + 255) / 256, 256>>>(x);
    k_edge_agg<<<(NE * 32 + 255) / 256, 256>>>(ei, x);

    k_rec<0><<<GRID_REC, NTH, SMEM_L0>>>(w_ih0, w_hh0, b_ih0, b_hh0,
                                         gcn_w, gcn_b, nullptr, nullptr, nullptr, nullptr,
                                         x, nullptr);
    k_rec<1><<<GRID_REC, NTH, SMEM_L1>>>(w_ih1, w_hh1, b_ih1, b_hh1,
                                         nullptr, nullptr, attn_w, attn_b, fc_w, fc_b,
                                         x, out);
}

// round 12
// speedup vs baseline: 1.8976x; 1.0973x over previous
#include <cuda_runtime.h>
#include <cuda_bf16.h>
#include <math.h>

#define NN 10000      // nodes
#define TT 12         // seq len
#define FIN 16        // in channels
#define HH 64         // hidden
#define K3 192        // 3*H
#define NE 160000     // edges
#define NT (NN*TT)    // 120000 rows
#define MB 80         // nodes per block (10000 = 125 * 80)
#define GRID_REC 125
#define NTH 768       // 24 warps: 2 K-halves x 12 N-role warps

typedef unsigned int u32;
typedef unsigned long long u64;

// ---------------- scratch (device globals; no allocation allowed) ----------
__device__ float g_deg[NN];
__device__ float g_agg[NN * TT * FIN];
__device__ u32  g_hap[NN * TT * (HH / 2)];   // packed bf16 hi-pairs (h1)

// ---------------- helpers ----------------------------------------------------
__device__ __forceinline__ float tanh_fast(float x) {
    float y; asm("tanh.approx.f32 %0, %1;" : "=f"(y) : "f"(x)); return y;
}
__device__ __forceinline__ float sigmoid_fast(float x) {
    return fmaf(0.5f, tanh_fast(0.5f * x), 0.5f);
}
__device__ __forceinline__ u32 pack2(__nv_bfloat16 a, __nv_bfloat16 b) {
    return (u32)__bfloat16_as_ushort(a) | ((u32)__bfloat16_as_ushort(b) << 16);
}
__device__ __forceinline__ void split_bf16(float v, __nv_bfloat16& hi, __nv_bfloat16& lo) {
    hi = __float2bfloat16(v);
    lo = __float2bfloat16(v - __bfloat162float(hi));
}
__device__ __forceinline__ void mma16816(float* c, const u32* a, u32 b0, u32 b1) {
    asm volatile(
        "mma.sync.aligned.m16n8k16.row.col.f32.bf16.bf16.f32 "
        "{%0,%1,%2,%3}, {%4,%5,%6,%7}, {%8,%9}, {%0,%1,%2,%3};"
        : "+f"(c[0]), "+f"(c[1]), "+f"(c[2]), "+f"(c[3])
        : "r"(a[0]), "r"(a[1]), "r"(a[2]), "r"(a[3]), "r"(b0), "r"(b1));
}
__device__ __forceinline__ void ldm4(u32* r, u32 saddr) {
    asm volatile("ldmatrix.sync.aligned.m8n8.x4.shared.b16 {%0,%1,%2,%3}, [%4];"
                 : "=r"(r[0]), "=r"(r[1]), "=r"(r[2]), "=r"(r[3]) : "r"(saddr));
}

// ---------------- degree / prep --------------------------------------------
__global__ void k_deg_init() {
    int i = blockIdx.x * blockDim.x + threadIdx.x;
    if (i < NN) g_deg[i] = 1.0f;
}
__global__ void k_deg_edge(const int* __restrict__ ei) {
    int e = blockIdx.x * blockDim.x + threadIdx.x;
    if (e < NE) atomicAdd(&g_deg[ei[NE + e]], 1.0f);
}
__global__ void k_agg_init(const float* __restrict__ x) {
    int idx = blockIdx.x * blockDim.x + threadIdx.x;
    if (idx >= NN * TT * 4) return;
    int n = idx / (TT * 4);
    int r = idx - n * (TT * 4);
    int t = r >> 2, f4 = r & 3;
    float di = rsqrtf(g_deg[n]);
    float c = di * di;
    float4 v = reinterpret_cast<const float4*>(x)[((size_t)t * NN + n) * 4 + f4];
    v.x *= c; v.y *= c; v.z *= c; v.w *= c;
    reinterpret_cast<float4*>(g_agg)[idx] = v;
}
__global__ void k_edge_agg(const int* __restrict__ ei, const float* __restrict__ x) {
    int gt = blockIdx.x * blockDim.x + threadIdx.x;
    int e = gt >> 5, lane = gt & 31;
    if (e >= NE) return;
    int s = ei[e];
    int d = ei[NE + e];
    float c = rsqrtf(g_deg[s]) * rsqrtf(g_deg[d]);
    const float4* x4 = reinterpret_cast<const float4*>(x);
    float4* dst4 = reinterpret_cast<float4*>(&g_agg[(size_t)d * (TT * FIN)]);
#pragma unroll
    for (int g = lane; g < 48; g += 32) {
        int t = g >> 2, f4 = g & 3;
        float4 v = x4[((size_t)t * NN + s) * 4 + f4];
        asm volatile("red.global.add.v4.f32 [%0], {%1, %2, %3, %4};"
                     :: "l"(dst4 + g), "f"(v.x * c), "f"(v.y * c), "f"(v.z * c), "f"(v.w * c)
                     : "memory");
    }
}

// ---------------- fused HMMA GRU layers --------------------------------------
// 24 warps = 2 K-halves x {8 rz + 2 xn + 2 hn}.
// rz gates: SINGLE-term bf16 weights (sigmoid-damped path).
// n gates : 2-term (w_hi + w_lo) weights (tanh path, direct contributor).
#define OFF_AHI  0               // bf16 A tile [80 x 256B]: X half | H half
#define OFF_GRZ0 20480           // fp32 [80][128] swizzled, K-half 0
#define OFF_GRZ1 61440           // K-half 1
#define OFF_GX0  102400          // fp32 [80][64]
#define OFF_GX1  122880
#define OFF_GH0  143360
#define OFF_GH1  163840
#define OFF_HS   184320          // fp32 h state [80][64]
#define OFF_B    204800          // biases: 256 floats
#define OFF_EXT  205824
#define SMEM_L0 (OFF_EXT + 4096 + 256)
#define SMEM_L1 (OFF_EXT + 20480 + 640 + 256 + 256 + 16)

// TERMS = 1: acc += a*b_hi only.  TERMS = 2: acc += a*b_hi + a*b_lo.
template<int KKS, int NTS, int TERMS>
__device__ __forceinline__ void mma_m_tile(
    u32 a_base, int kbyte, int swrow, int kk0,
    const u32* bh, const u32* bl, float* acc)
{
#pragma unroll
    for (int q = 0; q < NTS * 4; q++) acc[q] = 0.f;
#pragma unroll
    for (int kk = 0; kk < KKS; kk++) {
        u32 off = (u32)((((kk + kk0) * 32) + kbyte) ^ swrow);
        u32 ah[4];
        ldm4(ah, a_base + off);
#pragma unroll
        for (int nt = 0; nt < NTS; nt++) {
            int f = kk * NTS + nt;
            mma16816(acc + nt * 4, ah, bh[2 * f], bh[2 * f + 1]);
            if (TERMS == 2)
                mma16816(acc + nt * 4, ah, bl[2 * f], bl[2 * f + 1]);
        }
    }
}

template<int L>
__global__ __launch_bounds__(NTH, 1) void k_rec(
    const float* __restrict__ wih, const float* __restrict__ whh,
    const float* __restrict__ bih, const float* __restrict__ bhh,
    const float* __restrict__ gwp, const float* __restrict__ gbp,
    const float* __restrict__ awp, const float* __restrict__ abp,
    const float* __restrict__ fwp, const float* __restrict__ fbp,
    const float* __restrict__ x,   float* __restrict__ outv)
{
    extern __shared__ __align__(16) char sm[];
    char* AHI  = sm + OFF_AHI;
    char* GRZ0 = sm + OFF_GRZ0;
    char* GRZ1 = sm + OFF_GRZ1;
    char* GX0  = sm + OFF_GX0;
    char* GX1  = sm + OFF_GX1;
    char* GH0  = sm + OFF_GH0;
    char* GH1  = sm + OFF_GH1;
    float* hS   = (float*)(sm + OFF_HS);
    float* bias = (float*)(sm + OFF_B);
    float* gwS = (float*)(sm + OFF_EXT);
    float* gbS = (float*)(sm + OFF_EXT + 4096);
    float* ctx = (float*)(sm + OFF_EXT);
    float* mS  = (float*)(sm + OFF_EXT + 20480);
    float* ZS  = (float*)(sm + OFF_EXT + 20480 + 320);
    float* awS = (float*)(sm + OFF_EXT + 21120);
    float* fwS = (float*)(sm + OFF_EXT + 21376);
    float* scS = (float*)(sm + OFF_EXT + 21632);

    int tid = threadIdx.x, wid = tid >> 5, lid = tid & 31;
    int g = lid >> 2, tg = lid & 3;
    int node0 = blockIdx.x * MB;
    int wl = wid % 12;          // N-role warp index
    int half = wid / 12;        // K-half

    if (tid < 128) bias[tid] = bih[tid] + bhh[tid];
    else if (tid < 192) bias[tid] = bih[tid];
    else if (tid < 256) bias[tid] = bhh[tid - 64];

    if (L == 0) {
        for (int i = tid; i < FIN * HH; i += NTH) gwS[i] = gwp[i];
        if (tid >= 256 && tid < 320) gbS[tid - 256] = gbp[tid - 256];
    } else {
        for (int i = tid; i < MB * 64; i += NTH) ctx[i] = 0.0f;
        if (tid >= 256 && tid < 256 + MB) { mS[tid - 256] = -3.0e38f; ZS[tid - 256] = 0.0f; }
        if (tid >= 384 && tid < 448) { awS[tid - 384] = awp[tid - 384]; fwS[tid - 384] = fwp[tid - 384]; }
        if (tid == 448) scS[0] = abp[0];
    }

    {
        uint4 z = make_uint4(0, 0, 0, 0);
        for (int i = tid; i < 1280; i += NTH) ((uint4*)AHI)[i] = z;
        for (int i = tid; i < MB * 64; i += NTH) hS[i] = 0.0f;
    }

    bool is_rz = wl < 8;
    int role = is_rz ? 0 : (wl < 10 ? 1 : 2);
    int kk0 = is_rz ? half * 4 : half * 2;

    // persistent B fragments: w_hi always; w_lo only for n-gate warps
    u32 bh[16], bl[16];
#pragma unroll
    for (int f = 0; f < 8; f++) {
        int kk = is_rz ? (f >> 1) : (f >> 2);
        int nt = is_rz ? (f & 1)  : (f & 3);
        int nrow;
        if (role == 0)      nrow = wl * 16 + nt * 8 + g;
        else if (role == 1) nrow = 128 + (wl - 8) * 32 + nt * 8 + g;
        else                nrow = 128 + (wl - 10) * 32 + nt * 8 + g;
#pragma unroll
        for (int r = 0; r < 2; r++) {
            int k = (kk + kk0) * 16 + tg * 2 + r * 8;
            float w0, w1;
            if (role == 0) {
                if (k < 64) { w0 = wih[nrow * 64 + k];      w1 = wih[nrow * 64 + k + 1]; }
                else        { w0 = whh[nrow * 64 + k - 64]; w1 = whh[nrow * 64 + k - 63]; }
            } else if (role == 1) {
                w0 = wih[nrow * 64 + k]; w1 = wih[nrow * 64 + k + 1];
            } else {
                w0 = whh[nrow * 64 + k]; w1 = whh[nrow * 64 + k + 1];
            }
            __nv_bfloat16 h0, l0, h1, l1;
            split_bf16(w0, h0, l0);
            split_bf16(w1, h1, l1);
            bh[2 * f + r] = pack2(h0, h1);
            bl[2 * f + r] = pack2(l0, l1);
        }
    }

    int aoff = (role == 2) ? 128 : 0;
    int quad = lid >> 3;
    int rloc = (lid & 7) + ((quad & 1) << 3);
    int kbyte = (quad >> 1) << 4;
    int swrow = (rloc & 7) << 4;
    u32 AHI_s = (u32)__cvta_generic_to_shared(AHI);

    float aw0 = 0.f, aw1 = 0.f, ab = 0.f;
    __syncthreads();
    if (L == 1) { aw0 = awS[2 * lid]; aw1 = awS[2 * lid + 1]; ab = scS[0]; }

    // stage X(tt) into the X half of the A tile (bf16 hi only, swizzled)
    auto stage_x = [&](int tt) {
        if (L == 0) {
            for (int i = tid; i < MB * 16; i += NTH) {
                int m = i >> 4, j = i & 15;
                const float4* ar = reinterpret_cast<const float4*>(
                    &g_agg[(((size_t)(node0 + m)) * TT + tt) * 16]);
                float4 a0 = ar[0], a1 = ar[1], a2 = ar[2], a3 = ar[3];
                float s0 = gbS[4 * j], s1 = gbS[4 * j + 1], s2 = gbS[4 * j + 2], s3 = gbS[4 * j + 3];
#pragma unroll
                for (int f = 0; f < 16; f++) {
                    float av;
                    if (f < 4) av = ((const float*)&a0)[f];
                    else if (f < 8) av = ((const float*)&a1)[f - 4];
                    else if (f < 12) av = ((const float*)&a2)[f - 8];
                    else av = ((const float*)&a3)[f - 12];
                    const float4 wv = reinterpret_cast<const float4*>(gwS)[f * 16 + j];
                    s0 = fmaf(av, wv.x, s0);
                    s1 = fmaf(av, wv.y, s1);
                    s2 = fmaf(av, wv.z, s2);
                    s3 = fmaf(av, wv.w, s3);
                }
                s0 = fmaxf(s0, 0.f); s1 = fmaxf(s1, 0.f);
                s2 = fmaxf(s2, 0.f); s3 = fmaxf(s3, 0.f);
                uint2 phv;
                phv.x = pack2(__float2bfloat16(s0), __float2bfloat16(s1));
                phv.y = pack2(__float2bfloat16(s2), __float2bfloat16(s3));
                int byt = m * 256 + ((8 * j) ^ ((m & 7) << 4));
                *(uint2*)(AHI + byt) = phv;
            }
        } else {
            const uint2* in8 = reinterpret_cast<const uint2*>(g_hap);
            for (int i = tid; i < MB * 16; i += NTH) {
                int m = i >> 4, j = i & 15;
                uint2 v = in8[((size_t)(node0 + m) * TT + tt) * 16 + j];
                int byt = m * 256 + ((8 * j) ^ ((m & 7) << 4));
                *(uint2*)(AHI + byt) = v;
            }
        }
    };

    stage_x(0);
    __syncthreads();

    for (int t = 0; t < TT; t++) {
        // ---- MMA: 5 m-tiles of 16 rows, each warp its K-half ----
        for (int m = 0; m < 5; m++) {
            float acc[16];
            u32 rowb = (u32)((m * 16 + rloc) * 256 + aoff);
            if (is_rz) mma_m_tile<4, 2, 1>(AHI_s + rowb, kbyte, swrow, kk0, bh, bl, acc);
            else       mma_m_tile<2, 4, 2>(AHI_s + rowb, kbyte, swrow, kk0, bh, bl, acc);

            int row0 = m * 16 + g;
            int swG = g << 5;
            if (role == 0) {
                char* Gp = half ? GRZ1 : GRZ0;
#pragma unroll
                for (int nt = 0; nt < 2; nt++) {
                    int b = (4 * (wl * 16 + nt * 8 + tg * 2)) ^ swG;
                    *(float2*)(Gp + row0 * 512 + b)       = make_float2(acc[nt * 4 + 0], acc[nt * 4 + 1]);
                    *(float2*)(Gp + (row0 + 8) * 512 + b) = make_float2(acc[nt * 4 + 2], acc[nt * 4 + 3]);
                }
            } else {
                char* Gp = (role == 1) ? (half ? GX1 : GX0) : (half ? GH1 : GH0);
                int wb = (role == 1) ? (wl - 8) : (wl - 10);
#pragma unroll
                for (int nt = 0; nt < 4; nt++) {
                    int b = (4 * (wb * 32 + nt * 8 + tg * 2)) ^ swG;
                    *(float2*)(Gp + row0 * 256 + b)       = make_float2(acc[nt * 4 + 0], acc[nt * 4 + 1]);
                    *(float2*)(Gp + (row0 + 8) * 256 + b) = make_float2(acc[nt * 4 + 2], acc[nt * 4 + 3]);
                }
            }
        }
        __syncthreads();

        // ---- gates (+ L1: online-softmax attention); sum K-half partials ----
        for (int p = tid; p < MB * 32; p += NTH) {
            int row = p >> 5, jp = p & 31;
            int sw = (row & 7) << 5;
            int o = (8 * jp) ^ sw;
            float2 rva = *(float2*)(GRZ0 + row * 512 + o);
            float2 rvb = *(float2*)(GRZ1 + row * 512 + o);
            float2 zva = *(float2*)(GRZ0 + row * 512 + 256 + o);
            float2 zvb = *(float2*)(GRZ1 + row * 512 + 256 + o);
            float2 xva = *(float2*)(GX0 + row * 256 + o);
            float2 xvb = *(float2*)(GX1 + row * 256 + o);
            float2 hva = *(float2*)(GH0 + row * 256 + o);
            float2 hvb = *(float2*)(GH1 + row * 256 + o);
            float rx = rva.x + rvb.x, ry = rva.y + rvb.y;
            float zx = zva.x + zvb.x, zy = zva.y + zvb.y;
            float xx = xva.x + xvb.x, xy = xva.y + xvb.y;
            float hx = hva.x + hvb.x, hy = hva.y + hvb.y;
            int i0 = 2 * jp;
            float hp0 = hS[row * 64 + i0], hp1 = hS[row * 64 + i0 + 1];
            float r0 = sigmoid_fast(rx + bias[i0]);
            float r1 = sigmoid_fast(ry + bias[i0 + 1]);
            float z0 = sigmoid_fast(zx + bias[64 + i0]);
            float z1 = sigmoid_fast(zy + bias[64 + i0 + 1]);
            float n0 = tanh_fast(xx + bias[128 + i0]     + r0 * (hx + bias[192 + i0]));
            float n1 = tanh_fast(xy + bias[128 + i0 + 1] + r1 * (hy + bias[192 + i0 + 1]));
            float o0 = fmaf(z0, hp0 - n0, n0);
            float o1 = fmaf(z1, hp1 - n1, n1);
            hS[row * 64 + i0] = o0;
            hS[row * 64 + i0 + 1] = o1;
            u32 hip = pack2(__float2bfloat16(o0), __float2bfloat16(o1));
            int ba = row * 256 + 128 + ((4 * jp) ^ ((row & 7) << 4));
            *(u32*)(AHI + ba) = hip;
            if (L == 0) {
                g_hap[((size_t)(node0 + row) * TT + t) * 32 + jp] = hip;
            } else {
                float sc = o0 * aw0 + o1 * aw1;
#pragma unroll
                for (int of = 16; of > 0; of >>= 1) sc += __shfl_xor_sync(0xffffffffu, sc, of);
                sc += ab;
                float m_old = mS[row];
                float mn = fmaxf(m_old, sc);
                float ea = __expf(m_old - mn);
                float eb = __expf(sc - mn);
                ctx[row * 64 + i0]     = ctx[row * 64 + i0]     * ea + eb * o0;
                ctx[row * 64 + i0 + 1] = ctx[row * 64 + i0 + 1] * ea + eb * o1;
                if (jp == 0) { mS[row] = mn; ZS[row] = ZS[row] * ea + eb; }
            }
        }
        // ---- overlap: stage next timestep's X while gates warps drain ----
        if (t + 1 < TT) stage_x(t + 1);
        __syncthreads();
    }

    if (L == 1) {
        float fw0 = fwS[2 * lid], fw1 = fwS[2 * lid + 1];
        for (int row = wid; row < MB; row += 24) {
            float v = ctx[row * 64 + 2 * lid] * fw0 + ctx[row * 64 + 2 * lid + 1] * fw1;
#pragma unroll
            for (int of = 16; of > 0; of >>= 1) v += __shfl_xor_sync(0xffffffffu, v, of);
            if (lid == 0) {
                int node = node0 + row;
                float last = x[((size_t)(TT - 1) * NN + node) * FIN];
                outv[node] = last + v / ZS[row] + fbp[0];
            }
        }
    }
}

// ---------------- launch ----------------------------------------------------
extern "C" void kernel_launch(void* const* d_in, const int* in_sizes, int n_in,
                              void* d_out, int out_size) {
    const float* x      = (const float*)d_in[0];
    const int*   ei     = (const int*)  d_in[1];
    const float* gcn_w  = (const float*)d_in[2];
    const float* gcn_b  = (const float*)d_in[3];
    const float* w_ih0  = (const float*)d_in[4];
    const float* w_hh0  = (const float*)d_in[5];
    const float* b_ih0  = (const float*)d_in[6];
    const float* b_hh0  = (const float*)d_in[7];
    const float* w_ih1  = (const float*)d_in[8];
    const float* w_hh1  = (const float*)d_in[9];
    const float* b_ih1  = (const float*)d_in[10];
    const float* b_hh1  = (const float*)d_in[11];
    const float* attn_w = (const float*)d_in[12];
    const float* attn_b = (const float*)d_in[13];
    const float* fc_w   = (const float*)d_in[14];
    const float* fc_b   = (const float*)d_in[15];
    float* out = (float*)d_out;

    cudaFuncSetAttribute(k_rec<0>, cudaFuncAttributeMaxDynamicSharedMemorySize, SMEM_L0);
    cudaFuncSetAttribute(k_rec<1>, cudaFuncAttributeMaxDynamicSharedMemorySize, SMEM_L1);

    k_deg_init<<<(NN + 255) / 256, 256>>>();
    k_deg_edge<<<(NE + 255) / 256, 256>>>(ei);
    k_agg_init<<<(NN * TT * 4 + 255) / 256, 256>>>(x);
    k_edge_agg<<<(NE * 32 + 255) / 256, 256>>>(ei, x);

    k_rec<0><<<GRID_REC, NTH, SMEM_L0>>>(w_ih0, w_hh0, b_ih0, b_hh0,
                                         gcn_w, gcn_b, nullptr, nullptr, nullptr, nullptr,
                                         x, nullptr);
    k_rec<1><<<GRID_REC, NTH, SMEM_L1>>>(w_ih1, w_hh1, b_ih1, b_hh1,
                                         nullptr, nullptr, attn_w, attn_b, fc_w, fc_b,
                                         x, out);
}

// round 13
// speedup vs baseline: 2.0204x; 1.0647x over previous
#include <cuda_runtime.h>
#include <cuda_bf16.h>
#include <math.h>

#define NN 10000      // nodes
#define TT 12         // seq len
#define FIN 16        // in channels
#define HH 64         // hidden
#define K3 192        // 3*H
#define NE 160000     // edges
#define NT (NN*TT)    // 120000 rows
#define MB 80         // nodes per block (10000 = 125 * 80)
#define GRID_REC 125
#define NTH 768       // 24 warps: 2 K-halves x 12 N-role warps

typedef unsigned int u32;
typedef unsigned long long u64;

// ---------------- scratch (device globals; no allocation allowed) ----------
__device__ float g_deg[NN];
__device__ float g_agg[NN * TT * FIN];
__device__ u32  g_hap[NN * TT * (HH / 2)];   // packed bf16 hi-pairs (h1)

// ---------------- helpers ----------------------------------------------------
__device__ __forceinline__ float tanh_fast(float x) {
    float y; asm("tanh.approx.f32 %0, %1;" : "=f"(y) : "f"(x)); return y;
}
__device__ __forceinline__ float sigmoid_fast(float x) {
    return fmaf(0.5f, tanh_fast(0.5f * x), 0.5f);
}
__device__ __forceinline__ u32 pack2(__nv_bfloat16 a, __nv_bfloat16 b) {
    return (u32)__bfloat16_as_ushort(a) | ((u32)__bfloat16_as_ushort(b) << 16);
}
__device__ __forceinline__ void mma16816(float* c, const u32* a, u32 b0, u32 b1) {
    asm volatile(
        "mma.sync.aligned.m16n8k16.row.col.f32.bf16.bf16.f32 "
        "{%0,%1,%2,%3}, {%4,%5,%6,%7}, {%8,%9}, {%0,%1,%2,%3};"
        : "+f"(c[0]), "+f"(c[1]), "+f"(c[2]), "+f"(c[3])
        : "r"(a[0]), "r"(a[1]), "r"(a[2]), "r"(a[3]), "r"(b0), "r"(b1));
}
__device__ __forceinline__ void ldm4(u32* r, u32 saddr) {
    asm volatile("ldmatrix.sync.aligned.m8n8.x4.shared.b16 {%0,%1,%2,%3}, [%4];"
                 : "=r"(r[0]), "=r"(r[1]), "=r"(r[2]), "=r"(r[3]) : "r"(saddr));
}

// ---------------- degree / prep --------------------------------------------
__global__ void k_deg_init() {
    int i = blockIdx.x * blockDim.x + threadIdx.x;
    if (i < NN) g_deg[i] = 1.0f;
}
__global__ void k_deg_edge(const int* __restrict__ ei) {
    int e = blockIdx.x * blockDim.x + threadIdx.x;
    if (e < NE) atomicAdd(&g_deg[ei[NE + e]], 1.0f);
}
__global__ void k_agg_init(const float* __restrict__ x) {
    int idx = blockIdx.x * blockDim.x + threadIdx.x;
    if (idx >= NN * TT * 4) return;
    int n = idx / (TT * 4);
    int r = idx - n * (TT * 4);
    int t = r >> 2, f4 = r & 3;
    float di = rsqrtf(g_deg[n]);
    float c = di * di;
    float4 v = reinterpret_cast<const float4*>(x)[((size_t)t * NN + n) * 4 + f4];
    v.x *= c; v.y *= c; v.z *= c; v.w *= c;
    reinterpret_cast<float4*>(g_agg)[idx] = v;
}
__global__ void k_edge_agg(const int* __restrict__ ei, const float* __restrict__ x) {
    int gt = blockIdx.x * blockDim.x + threadIdx.x;
    int e = gt >> 5, lane = gt & 31;
    if (e >= NE) return;
    int s = ei[e];
    int d = ei[NE + e];
    float c = rsqrtf(g_deg[s]) * rsqrtf(g_deg[d]);
    const float4* x4 = reinterpret_cast<const float4*>(x);
    float4* dst4 = reinterpret_cast<float4*>(&g_agg[(size_t)d * (TT * FIN)]);
#pragma unroll
    for (int g = lane; g < 48; g += 32) {
        int t = g >> 2, f4 = g & 3;
        float4 v = x4[((size_t)t * NN + s) * 4 + f4];
        asm volatile("red.global.add.v4.f32 [%0], {%1, %2, %3, %4};"
                     :: "l"(dst4 + g), "f"(v.x * c), "f"(v.y * c), "f"(v.z * c), "f"(v.w * c)
                     : "memory");
    }
}

// ---------------- fused HMMA GRU layers --------------------------------------
// 24 warps = 2 K-halves x {8 rz + 2 xn + 2 hn}. Single-term bf16 weights
// everywhere (validated: weight rounding contributes ~3e-7 to rel_err).
// Every warp: 8 MMA per m-tile, identical inner loop.
#define OFF_AHI  0               // bf16 A tile [80 x 256B]: X half | H half
#define OFF_GRZ0 20480           // fp32 [80][128] swizzled, K-half 0
#define OFF_GRZ1 61440           // K-half 1
#define OFF_GX0  102400          // fp32 [80][64]
#define OFF_GX1  122880
#define OFF_GH0  143360
#define OFF_GH1  163840
#define OFF_HS   184320          // fp32 h state [80][64]
#define OFF_B    204800          // biases: 256 floats
#define OFF_EXT  205824
#define SMEM_L0 (OFF_EXT + 4096 + 256)
#define SMEM_L1 (OFF_EXT + 20480 + 640 + 256 + 256 + 16)

// single-term m-tile: acc += a * b_hi
template<int KKS, int NTS>
__device__ __forceinline__ void mma_m_tile(
    u32 a_base, int kbyte, int swrow, int kk0,
    const u32* bh, float* acc)
{
#pragma unroll
    for (int q = 0; q < NTS * 4; q++) acc[q] = 0.f;
#pragma unroll
    for (int kk = 0; kk < KKS; kk++) {
        u32 off = (u32)((((kk + kk0) * 32) + kbyte) ^ swrow);
        u32 ah[4];
        ldm4(ah, a_base + off);
#pragma unroll
        for (int nt = 0; nt < NTS; nt++) {
            int f = kk * NTS + nt;
            mma16816(acc + nt * 4, ah, bh[2 * f], bh[2 * f + 1]);
        }
    }
}

template<int L>
__global__ __launch_bounds__(NTH, 1) void k_rec(
    const float* __restrict__ wih, const float* __restrict__ whh,
    const float* __restrict__ bih, const float* __restrict__ bhh,
    const float* __restrict__ gwp, const float* __restrict__ gbp,
    const float* __restrict__ awp, const float* __restrict__ abp,
    const float* __restrict__ fwp, const float* __restrict__ fbp,
    const float* __restrict__ x,   float* __restrict__ outv)
{
    extern __shared__ __align__(16) char sm[];
    char* AHI  = sm + OFF_AHI;
    char* GRZ0 = sm + OFF_GRZ0;
    char* GRZ1 = sm + OFF_GRZ1;
    char* GX0  = sm + OFF_GX0;
    char* GX1  = sm + OFF_GX1;
    char* GH0  = sm + OFF_GH0;
    char* GH1  = sm + OFF_GH1;
    float* hS   = (float*)(sm + OFF_HS);
    float* bias = (float*)(sm + OFF_B);
    float* gwS = (float*)(sm + OFF_EXT);
    float* gbS = (float*)(sm + OFF_EXT + 4096);
    float* ctx = (float*)(sm + OFF_EXT);
    float* mS  = (float*)(sm + OFF_EXT + 20480);
    float* ZS  = (float*)(sm + OFF_EXT + 20480 + 320);
    float* awS = (float*)(sm + OFF_EXT + 21120);
    float* fwS = (float*)(sm + OFF_EXT + 21376);
    float* scS = (float*)(sm + OFF_EXT + 21632);

    int tid = threadIdx.x, wid = tid >> 5, lid = tid & 31;
    int g = lid >> 2, tg = lid & 3;
    int node0 = blockIdx.x * MB;
    int wl = wid % 12;          // N-role warp index
    int half = wid / 12;        // K-half

    if (tid < 128) bias[tid] = bih[tid] + bhh[tid];
    else if (tid < 192) bias[tid] = bih[tid];
    else if (tid < 256) bias[tid] = bhh[tid - 64];

    if (L == 0) {
        for (int i = tid; i < FIN * HH; i += NTH) gwS[i] = gwp[i];
        if (tid >= 256 && tid < 320) gbS[tid - 256] = gbp[tid - 256];
    } else {
        for (int i = tid; i < MB * 64; i += NTH) ctx[i] = 0.0f;
        if (tid >= 256 && tid < 256 + MB) { mS[tid - 256] = -3.0e38f; ZS[tid - 256] = 0.0f; }
        if (tid >= 384 && tid < 448) { awS[tid - 384] = awp[tid - 384]; fwS[tid - 384] = fwp[tid - 384]; }
        if (tid == 448) scS[0] = abp[0];
    }

    {
        uint4 z = make_uint4(0, 0, 0, 0);
        for (int i = tid; i < 1280; i += NTH) ((uint4*)AHI)[i] = z;
        for (int i = tid; i < MB * 64; i += NTH) hS[i] = 0.0f;
    }

    bool is_rz = wl < 8;
    int role = is_rz ? 0 : (wl < 10 ? 1 : 2);
    int kk0 = is_rz ? half * 4 : half * 2;

    // persistent B fragments: bf16 weights (hi only), 8 slots x 2 regs
    u32 bh[16];
#pragma unroll
    for (int f = 0; f < 8; f++) {
        int kk = is_rz ? (f >> 1) : (f >> 2);
        int nt = is_rz ? (f & 1)  : (f & 3);
        int nrow;
        if (role == 0)      nrow = wl * 16 + nt * 8 + g;
        else if (role == 1) nrow = 128 + (wl - 8) * 32 + nt * 8 + g;
        else                nrow = 128 + (wl - 10) * 32 + nt * 8 + g;
#pragma unroll
        for (int r = 0; r < 2; r++) {
            int k = (kk + kk0) * 16 + tg * 2 + r * 8;
            float w0, w1;
            if (role == 0) {
                if (k < 64) { w0 = wih[nrow * 64 + k];      w1 = wih[nrow * 64 + k + 1]; }
                else        { w0 = whh[nrow * 64 + k - 64]; w1 = whh[nrow * 64 + k - 63]; }
            } else if (role == 1) {
                w0 = wih[nrow * 64 + k]; w1 = wih[nrow * 64 + k + 1];
            } else {
                w0 = whh[nrow * 64 + k]; w1 = whh[nrow * 64 + k + 1];
            }
            bh[2 * f + r] = pack2(__float2bfloat16(w0), __float2bfloat16(w1));
        }
    }

    int aoff = (role == 2) ? 128 : 0;
    int quad = lid >> 3;
    int rloc = (lid & 7) + ((quad & 1) << 3);
    int kbyte = (quad >> 1) << 4;
    int swrow = (rloc & 7) << 4;
    u32 AHI_s = (u32)__cvta_generic_to_shared(AHI);

    float aw0 = 0.f, aw1 = 0.f, ab = 0.f;
    __syncthreads();
    if (L == 1) { aw0 = awS[2 * lid]; aw1 = awS[2 * lid + 1]; ab = scS[0]; }

    // stage X(tt) into the X half of the A tile (bf16, swizzled)
    auto stage_x = [&](int tt) {
        if (L == 0) {
            for (int i = tid; i < MB * 16; i += NTH) {
                int m = i >> 4, j = i & 15;
                const float4* ar = reinterpret_cast<const float4*>(
                    &g_agg[(((size_t)(node0 + m)) * TT + tt) * 16]);
                float4 a0 = ar[0], a1 = ar[1], a2 = ar[2], a3 = ar[3];
                float s0 = gbS[4 * j], s1 = gbS[4 * j + 1], s2 = gbS[4 * j + 2], s3 = gbS[4 * j + 3];
#pragma unroll
                for (int f = 0; f < 16; f++) {
                    float av;
                    if (f < 4) av = ((const float*)&a0)[f];
                    else if (f < 8) av = ((const float*)&a1)[f - 4];
                    else if (f < 12) av = ((const float*)&a2)[f - 8];
                    else av = ((const float*)&a3)[f - 12];
                    const float4 wv = reinterpret_cast<const float4*>(gwS)[f * 16 + j];
                    s0 = fmaf(av, wv.x, s0);
                    s1 = fmaf(av, wv.y, s1);
                    s2 = fmaf(av, wv.z, s2);
                    s3 = fmaf(av, wv.w, s3);
                }
                s0 = fmaxf(s0, 0.f); s1 = fmaxf(s1, 0.f);
                s2 = fmaxf(s2, 0.f); s3 = fmaxf(s3, 0.f);
                uint2 phv;
                phv.x = pack2(__float2bfloat16(s0), __float2bfloat16(s1));
                phv.y = pack2(__float2bfloat16(s2), __float2bfloat16(s3));
                int byt = m * 256 + ((8 * j) ^ ((m & 7) << 4));
                *(uint2*)(AHI + byt) = phv;
            }
        } else {
            const uint2* in8 = reinterpret_cast<const uint2*>(g_hap);
            for (int i = tid; i < MB * 16; i += NTH) {
                int m = i >> 4, j = i & 15;
                uint2 v = in8[((size_t)(node0 + m) * TT + tt) * 16 + j];
                int byt = m * 256 + ((8 * j) ^ ((m & 7) << 4));
                *(uint2*)(AHI + byt) = v;
            }
        }
    };

    stage_x(0);
    __syncthreads();

    for (int t = 0; t < TT; t++) {
        // ---- MMA: 5 m-tiles of 16 rows, each warp its K-half ----
        for (int m = 0; m < 5; m++) {
            float acc[16];
            u32 rowb = (u32)((m * 16 + rloc) * 256 + aoff);
            if (is_rz) mma_m_tile<4, 2>(AHI_s + rowb, kbyte, swrow, kk0, bh, acc);
            else       mma_m_tile<2, 4>(AHI_s + rowb, kbyte, swrow, kk0, bh, acc);

            int row0 = m * 16 + g;
            int swG = g << 5;
            if (role == 0) {
                char* Gp = half ? GRZ1 : GRZ0;
#pragma unroll
                for (int nt = 0; nt < 2; nt++) {
                    int b = (4 * (wl * 16 + nt * 8 + tg * 2)) ^ swG;
                    *(float2*)(Gp + row0 * 512 + b)       = make_float2(acc[nt * 4 + 0], acc[nt * 4 + 1]);
                    *(float2*)(Gp + (row0 + 8) * 512 + b) = make_float2(acc[nt * 4 + 2], acc[nt * 4 + 3]);
                }
            } else {
                char* Gp = (role == 1) ? (half ? GX1 : GX0) : (half ? GH1 : GH0);
                int wb = (role == 1) ? (wl - 8) : (wl - 10);
#pragma unroll
                for (int nt = 0; nt < 4; nt++) {
                    int b = (4 * (wb * 32 + nt * 8 + tg * 2)) ^ swG;
                    *(float2*)(Gp + row0 * 256 + b)       = make_float2(acc[nt * 4 + 0], acc[nt * 4 + 1]);
                    *(float2*)(Gp + (row0 + 8) * 256 + b) = make_float2(acc[nt * 4 + 2], acc[nt * 4 + 3]);
                }
            }
        }
        __syncthreads();

        // ---- gates (+ L1: online-softmax attention); sum K-half partials ----
        for (int p = tid; p < MB * 32; p += NTH) {
            int row = p >> 5, jp = p & 31;
            int sw = (row & 7) << 5;
            int o = (8 * jp) ^ sw;
            float2 rva = *(float2*)(GRZ0 + row * 512 + o);
            float2 rvb = *(float2*)(GRZ1 + row * 512 + o);
            float2 zva = *(float2*)(GRZ0 + row * 512 + 256 + o);
            float2 zvb = *(float2*)(GRZ1 + row * 512 + 256 + o);
            float2 xva = *(float2*)(GX0 + row * 256 + o);
            float2 xvb = *(float2*)(GX1 + row * 256 + o);
            float2 hva = *(float2*)(GH0 + row * 256 + o);
            float2 hvb = *(float2*)(GH1 + row * 256 + o);
            float rx = rva.x + rvb.x, ry = rva.y + rvb.y;
            float zx = zva.x + zvb.x, zy = zva.y + zvb.y;
            float xx = xva.x + xvb.x, xy = xva.y + xvb.y;
            float hx = hva.x + hvb.x, hy = hva.y + hvb.y;
            int i0 = 2 * jp;
            float hp0 = hS[row * 64 + i0], hp1 = hS[row * 64 + i0 + 1];
            float r0 = sigmoid_fast(rx + bias[i0]);
            float r1 = sigmoid_fast(ry + bias[i0 + 1]);
            float z0 = sigmoid_fast(zx + bias[64 + i0]);
            float z1 = sigmoid_fast(zy + bias[64 + i0 + 1]);
            float n0 = tanh_fast(xx + bias[128 + i0]     + r0 * (hx + bias[192 + i0]));
            float n1 = tanh_fast(xy + bias[128 + i0 + 1] + r1 * (hy + bias[192 + i0 + 1]));
            float o0 = fmaf(z0, hp0 - n0, n0);
            float o1 = fmaf(z1, hp1 - n1, n1);
            hS[row * 64 + i0] = o0;
            hS[row * 64 + i0 + 1] = o1;
            u32 hip = pack2(__float2bfloat16(o0), __float2bfloat16(o1));
            int ba = row * 256 + 128 + ((4 * jp) ^ ((row & 7) << 4));
            *(u32*)(AHI + ba) = hip;
            if (L == 0) {
                g_hap[((size_t)(node0 + row) * TT + t) * 32 + jp] = hip;
            } else {
                float sc = o0 * aw0 + o1 * aw1;
#pragma unroll
                for (int of = 16; of > 0; of >>= 1) sc += __shfl_xor_sync(0xffffffffu, sc, of);
                sc += ab;
                float m_old = mS[row];
                float mn = fmaxf(m_old, sc);
                float ea = __expf(m_old - mn);
                float eb = __expf(sc - mn);
                ctx[row * 64 + i0]     = ctx[row * 64 + i0]     * ea + eb * o0;
                ctx[row * 64 + i0 + 1] = ctx[row * 64 + i0 + 1] * ea + eb * o1;
                if (jp == 0) { mS[row] = mn; ZS[row] = ZS[row] * ea + eb; }
            }
        }
        // ---- overlap: stage next timestep's X while gates warps drain ----
        if (t + 1 < TT) stage_x(t + 1);
        __syncthreads();
    }

    if (L == 1) {
        float fw0 = fwS[2 * lid], fw1 = fwS[2 * lid + 1];
        for (int row = wid; row < MB; row += 24) {
            float v = ctx[row * 64 + 2 * lid] * fw0 + ctx[row * 64 + 2 * lid + 1] * fw1;
#pragma unroll
            for (int of = 16; of > 0; of >>= 1) v += __shfl_xor_sync(0xffffffffu, v, of);
            if (lid == 0) {
                int node = node0 + row;
                float last = x[((size_t)(TT - 1) * NN + node) * FIN];
                outv[node] = last + v / ZS[row] + fbp[0];
            }
        }
    }
}

// ---------------- launch ----------------------------------------------------
extern "C" void kernel_launch(void* const* d_in, const int* in_sizes, int n_in,
                              void* d_out, int out_size) {
    const float* x      = (const float*)d_in[0];
    const int*   ei     = (const int*)  d_in[1];
    const float* gcn_w  = (const float*)d_in[2];
    const float* gcn_b  = (const float*)d_in[3];
    const float* w_ih0  = (const float*)d_in[4];
    const float* w_hh0  = (const float*)d_in[5];
    const float* b_ih0  = (const float*)d_in[6];
    const float* b_hh0  = (const float*)d_in[7];
    const float* w_ih1  = (const float*)d_in[8];
    const float* w_hh1  = (const float*)d_in[9];
    const float* b_ih1  = (const float*)d_in[10];
    const float* b_hh1  = (const float*)d_in[11];
    const float* attn_w = (const float*)d_in[12];
    const float* attn_b = (const float*)d_in[13];
    const float* fc_w   = (const float*)d_in[14];
    const float* fc_b   = (const float*)d_in[15];
    float* out = (float*)d_out;

    cudaFuncSetAttribute(k_rec<0>, cudaFuncAttributeMaxDynamicSharedMemorySize, SMEM_L0);
    cudaFuncSetAttribute(k_rec<1>, cudaFuncAttributeMaxDynamicSharedMemorySize, SMEM_L1);

    k_deg_init<<<(NN + 255) / 256, 256>>>();
    k_deg_edge<<<(NE + 255) / 256, 256>>>(ei);
    k_agg_init<<<(NN * TT * 4 + 255) / 256, 256>>>(x);
    k_edge_agg<<<(NE * 32 + 255) / 256, 256>>>(ei, x);

    k_rec<0><<<GRID_REC, NTH, SMEM_L0>>>(w_ih0, w_hh0, b_ih0, b_hh0,
                                         gcn_w, gcn_b, nullptr, nullptr, nullptr, nullptr,
                                         x, nullptr);
    k_rec<1><<<GRID_REC, NTH, SMEM_L1>>>(w_ih1, w_hh1, b_ih1, b_hh1,
                                         nullptr, nullptr, attn_w, attn_b, fc_w, fc_b,
                                         x, out);
}

// round 14
// speedup vs baseline: 2.0867x; 1.0328x over previous
#include <cuda_runtime.h>
#include <cuda_bf16.h>
#include <math.h>

#define NN 10000      // nodes
#define TT 12         // seq len
#define FIN 16        // in channels
#define HH 64         // hidden
#define K3 192        // 3*H
#define NE 160000     // edges
#define NT (NN*TT)    // 120000 rows
#define MB 80         // nodes per block (10000 = 125 * 80)
#define GRID_REC 125
#define NTH 768       // 24 warps: 2 K-halves x 12 N-role warps

typedef unsigned int u32;
typedef unsigned long long u64;

// ---------------- scratch (device globals; no allocation allowed) ----------
__device__ float g_deg[NN];
__device__ u32  g_aggh[NN * TT * 8];         // packed bf16 agg: 16 per (n,t) row
__device__ u32  g_hap[NN * TT * (HH / 2)];   // packed bf16 hi-pairs (h1)

// ---------------- helpers ----------------------------------------------------
__device__ __forceinline__ float tanh_fast(float x) {
    float y; asm("tanh.approx.f32 %0, %1;" : "=f"(y) : "f"(x)); return y;
}
__device__ __forceinline__ float sigmoid_fast(float x) {
    return fmaf(0.5f, tanh_fast(0.5f * x), 0.5f);
}
__device__ __forceinline__ u32 pack2(__nv_bfloat16 a, __nv_bfloat16 b) {
    return (u32)__bfloat16_as_ushort(a) | ((u32)__bfloat16_as_ushort(b) << 16);
}
__device__ __forceinline__ u32 pack2f(float a, float b) {
    return pack2(__float2bfloat16(a), __float2bfloat16(b));
}
__device__ __forceinline__ void unp2(u32 p, float& a, float& b) {
    a = __bfloat162float(__ushort_as_bfloat16((unsigned short)(p & 0xffffu)));
    b = __bfloat162float(__ushort_as_bfloat16((unsigned short)(p >> 16)));
}
__device__ __forceinline__ void mma16816(float* c, const u32* a, u32 b0, u32 b1) {
    asm volatile(
        "mma.sync.aligned.m16n8k16.row.col.f32.bf16.bf16.f32 "
        "{%0,%1,%2,%3}, {%4,%5,%6,%7}, {%8,%9}, {%0,%1,%2,%3};"
        : "+f"(c[0]), "+f"(c[1]), "+f"(c[2]), "+f"(c[3])
        : "r"(a[0]), "r"(a[1]), "r"(a[2]), "r"(a[3]), "r"(b0), "r"(b1));
}
__device__ __forceinline__ void ldm4(u32* r, u32 saddr) {
    asm volatile("ldmatrix.sync.aligned.m8n8.x4.shared.b16 {%0,%1,%2,%3}, [%4];"
                 : "=r"(r[0]), "=r"(r[1]), "=r"(r[2]), "=r"(r[3]) : "r"(saddr));
}

// ---------------- degree / prep --------------------------------------------
__global__ void k_deg_init() {
    int i = blockIdx.x * blockDim.x + threadIdx.x;
    if (i < NN) g_deg[i] = 1.0f;
}
__global__ void k_deg_edge(const int* __restrict__ ei) {
    int e = blockIdx.x * blockDim.x + threadIdx.x;
    if (e < NE) atomicAdd(&g_deg[ei[NE + e]], 1.0f);
}
// agg init (bf16 packed): one thread = 8 values (half a (n,t) row)
__global__ void k_agg_init(const float* __restrict__ x) {
    int idx = blockIdx.x * blockDim.x + threadIdx.x;
    if (idx >= NN * TT * 2) return;
    int q = idx & 1;
    int nt = idx >> 1;
    int n = nt / TT, t = nt - n * TT;
    float di = rsqrtf(g_deg[n]);
    float c = di * di;
    const float4* xr = reinterpret_cast<const float4*>(&x[(((size_t)t * NN + n) * 16) + q * 8]);
    float4 v0 = xr[0], v1 = xr[1];
    uint4 o;
    o.x = pack2f(v0.x * c, v0.y * c);
    o.y = pack2f(v0.z * c, v0.w * c);
    o.z = pack2f(v1.x * c, v1.y * c);
    o.w = pack2f(v1.z * c, v1.w * c);
    reinterpret_cast<uint4*>(g_aggh)[idx] = o;
}
// edge scatter: warp per edge; 24 x red.v4.bf16x2 (8 values each)
__global__ void k_edge_agg(const int* __restrict__ ei, const float* __restrict__ x) {
    int gt = blockIdx.x * blockDim.x + threadIdx.x;
    int e = gt >> 5, lane = gt & 31;
    if (e >= NE || lane >= 24) return;
    int s = ei[e];
    int d = ei[NE + e];
    float c = rsqrtf(g_deg[s]) * rsqrtf(g_deg[d]);
    int t = lane >> 1, qh = lane & 1;
    const float4* xr = reinterpret_cast<const float4*>(&x[(((size_t)t * NN + s) * 16) + qh * 8]);
    float4 v0 = xr[0], v1 = xr[1];
    u32 p0 = pack2f(v0.x * c, v0.y * c);
    u32 p1 = pack2f(v0.z * c, v0.w * c);
    u32 p2 = pack2f(v1.x * c, v1.y * c);
    u32 p3 = pack2f(v1.z * c, v1.w * c);
    u32* dst = g_aggh + (size_t)d * (TT * 8) + lane * 4;
    asm volatile("red.global.add.noftz.v4.bf16x2 [%0], {%1, %2, %3, %4};"
                 :: "l"(dst), "r"(p0), "r"(p1), "r"(p2), "r"(p3) : "memory");
}

// ---------------- fused HMMA GRU layers --------------------------------------
// 24 warps = 2 K-halves x {8 rz + 2 xn + 2 hn}. Single-term bf16 weights.
#define OFF_AHI  0               // bf16 A tile [80 x 256B]: X half | H half
#define OFF_GRZ0 20480           // fp32 [80][128] swizzled, K-half 0
#define OFF_GRZ1 61440           // K-half 1
#define OFF_GX0  102400          // fp32 [80][64]
#define OFF_GX1  122880
#define OFF_GH0  143360
#define OFF_GH1  163840
#define OFF_HS   184320          // fp32 h state [80][64]
#define OFF_B    204800          // biases: 256 floats
#define OFF_EXT  205824
#define SMEM_L0 (OFF_EXT + 4096 + 256)
#define SMEM_L1 (OFF_EXT + 20480 + 640 + 256 + 256 + 16)

// single-term m-tile: acc += a * b
template<int KKS, int NTS>
__device__ __forceinline__ void mma_m_tile(
    u32 a_base, int kbyte, int swrow, int kk0,
    const u32* bh, float* acc)
{
#pragma unroll
    for (int q = 0; q < NTS * 4; q++) acc[q] = 0.f;
#pragma unroll
    for (int kk = 0; kk < KKS; kk++) {
        u32 off = (u32)((((kk + kk0) * 32) + kbyte) ^ swrow);
        u32 ah[4];
        ldm4(ah, a_base + off);
#pragma unroll
        for (int nt = 0; nt < NTS; nt++) {
            int f = kk * NTS + nt;
            mma16816(acc + nt * 4, ah, bh[2 * f], bh[2 * f + 1]);
        }
    }
}

template<int L>
__global__ __launch_bounds__(NTH, 1) void k_rec(
    const float* __restrict__ wih, const float* __restrict__ whh,
    const float* __restrict__ bih, const float* __restrict__ bhh,
    const float* __restrict__ gwp, const float* __restrict__ gbp,
    const float* __restrict__ awp, const float* __restrict__ abp,
    const float* __restrict__ fwp, const float* __restrict__ fbp,
    const float* __restrict__ x,   float* __restrict__ outv)
{
    extern __shared__ __align__(16) char sm[];
    char* AHI  = sm + OFF_AHI;
    char* GRZ0 = sm + OFF_GRZ0;
    char* GRZ1 = sm + OFF_GRZ1;
    char* GX0  = sm + OFF_GX0;
    char* GX1  = sm + OFF_GX1;
    char* GH0  = sm + OFF_GH0;
    char* GH1  = sm + OFF_GH1;
    float* hS   = (float*)(sm + OFF_HS);
    float* bias = (float*)(sm + OFF_B);
    float* gwS = (float*)(sm + OFF_EXT);
    float* gbS = (float*)(sm + OFF_EXT + 4096);
    float* ctx = (float*)(sm + OFF_EXT);
    float* mS  = (float*)(sm + OFF_EXT + 20480);
    float* ZS  = (float*)(sm + OFF_EXT + 20480 + 320);
    float* awS = (float*)(sm + OFF_EXT + 21120);
    float* fwS = (float*)(sm + OFF_EXT + 21376);
    float* scS = (float*)(sm + OFF_EXT + 21632);

    int tid = threadIdx.x, wid = tid >> 5, lid = tid & 31;
    int g = lid >> 2, tg = lid & 3;
    int node0 = blockIdx.x * MB;
    int wl = wid % 12;          // N-role warp index
    int half = wid / 12;        // K-half

    if (tid < 128) bias[tid] = bih[tid] + bhh[tid];
    else if (tid < 192) bias[tid] = bih[tid];
    else if (tid < 256) bias[tid] = bhh[tid - 64];

    if (L == 0) {
        for (int i = tid; i < FIN * HH; i += NTH) gwS[i] = gwp[i];
        if (tid >= 256 && tid < 320) gbS[tid - 256] = gbp[tid - 256];
    } else {
        for (int i = tid; i < MB * 64; i += NTH) ctx[i] = 0.0f;
        if (tid >= 256 && tid < 256 + MB) { mS[tid - 256] = -3.0e38f; ZS[tid - 256] = 0.0f; }
        if (tid >= 384 && tid < 448) { awS[tid - 384] = awp[tid - 384]; fwS[tid - 384] = fwp[tid - 384]; }
        if (tid == 448) scS[0] = abp[0];
    }

    {
        uint4 z = make_uint4(0, 0, 0, 0);
        for (int i = tid; i < 1280; i += NTH) ((uint4*)AHI)[i] = z;
        for (int i = tid; i < MB * 64; i += NTH) hS[i] = 0.0f;
    }

    bool is_rz = wl < 8;
    int role = is_rz ? 0 : (wl < 10 ? 1 : 2);
    int kk0 = is_rz ? half * 4 : half * 2;

    // persistent B fragments: bf16 weights, 8 slots x 2 regs
    u32 bh[16];
#pragma unroll
    for (int f = 0; f < 8; f++) {
        int kk = is_rz ? (f >> 1) : (f >> 2);
        int nt = is_rz ? (f & 1)  : (f & 3);
        int nrow;
        if (role == 0)      nrow = wl * 16 + nt * 8 + g;
        else if (role == 1) nrow = 128 + (wl - 8) * 32 + nt * 8 + g;
        else                nrow = 128 + (wl - 10) * 32 + nt * 8 + g;
#pragma unroll
        for (int r = 0; r < 2; r++) {
            int k = (kk + kk0) * 16 + tg * 2 + r * 8;
            float w0, w1;
            if (role == 0) {
                if (k < 64) { w0 = wih[nrow * 64 + k];      w1 = wih[nrow * 64 + k + 1]; }
                else        { w0 = whh[nrow * 64 + k - 64]; w1 = whh[nrow * 64 + k - 63]; }
            } else if (role == 1) {
                w0 = wih[nrow * 64 + k]; w1 = wih[nrow * 64 + k + 1];
            } else {
                w0 = whh[nrow * 64 + k]; w1 = whh[nrow * 64 + k + 1];
            }
            bh[2 * f + r] = pack2f(w0, w1);
        }
    }

    int aoff = (role == 2) ? 128 : 0;
    int quad = lid >> 3;
    int rloc = (lid & 7) + ((quad & 1) << 3);
    int kbyte = (quad >> 1) << 4;
    int swrow = (rloc & 7) << 4;
    u32 AHI_s = (u32)__cvta_generic_to_shared(AHI);

    float aw0 = 0.f, aw1 = 0.f, ab = 0.f;
    __syncthreads();
    if (L == 1) { aw0 = awS[2 * lid]; aw1 = awS[2 * lid + 1]; ab = scS[0]; }

    // stage X(tt) into the X half of the A tile (bf16, swizzled)
    auto stage_x = [&](int tt) {
        if (L == 0) {
            for (int i = tid; i < MB * 16; i += NTH) {
                int m = i >> 4, j = i & 15;
                const uint4* ar = reinterpret_cast<const uint4*>(
                    g_aggh + (((size_t)(node0 + m)) * TT + tt) * 8);
                uint4 qa = ar[0], qb = ar[1];
                float a[16];
                unp2(qa.x, a[0], a[1]);  unp2(qa.y, a[2], a[3]);
                unp2(qa.z, a[4], a[5]);  unp2(qa.w, a[6], a[7]);
                unp2(qb.x, a[8], a[9]);  unp2(qb.y, a[10], a[11]);
                unp2(qb.z, a[12], a[13]); unp2(qb.w, a[14], a[15]);
                float s0 = gbS[4 * j], s1 = gbS[4 * j + 1], s2 = gbS[4 * j + 2], s3 = gbS[4 * j + 3];
#pragma unroll
                for (int f = 0; f < 16; f++) {
                    const float4 wv = reinterpret_cast<const float4*>(gwS)[f * 16 + j];
                    s0 = fmaf(a[f], wv.x, s0);
                    s1 = fmaf(a[f], wv.y, s1);
                    s2 = fmaf(a[f], wv.z, s2);
                    s3 = fmaf(a[f], wv.w, s3);
                }
                s0 = fmaxf(s0, 0.f); s1 = fmaxf(s1, 0.f);
                s2 = fmaxf(s2, 0.f); s3 = fmaxf(s3, 0.f);
                uint2 phv;
                phv.x = pack2f(s0, s1);
                phv.y = pack2f(s2, s3);
                int byt = m * 256 + ((8 * j) ^ ((m & 7) << 4));
                *(uint2*)(AHI + byt) = phv;
            }
        } else {
            const uint2* in8 = reinterpret_cast<const uint2*>(g_hap);
            for (int i = tid; i < MB * 16; i += NTH) {
                int m = i >> 4, j = i & 15;
                uint2 v = in8[((size_t)(node0 + m) * TT + tt) * 16 + j];
                int byt = m * 256 + ((8 * j) ^ ((m & 7) << 4));
                *(uint2*)(AHI + byt) = v;
            }
        }
    };

    stage_x(0);
    __syncthreads();

    for (int t = 0; t < TT; t++) {
        // ---- MMA: 5 m-tiles of 16 rows, each warp its K-half ----
        for (int m = 0; m < 5; m++) {
            float acc[16];
            u32 rowb = (u32)((m * 16 + rloc) * 256 + aoff);
            if (is_rz) mma_m_tile<4, 2>(AHI_s + rowb, kbyte, swrow, kk0, bh, acc);
            else       mma_m_tile<2, 4>(AHI_s + rowb, kbyte, swrow, kk0, bh, acc);

            int row0 = m * 16 + g;
            int swG = g << 5;
            if (role == 0) {
                char* Gp = half ? GRZ1 : GRZ0;
#pragma unroll
                for (int nt = 0; nt < 2; nt++) {
                    int b = (4 * (wl * 16 + nt * 8 + tg * 2)) ^ swG;
                    *(float2*)(Gp + row0 * 512 + b)       = make_float2(acc[nt * 4 + 0], acc[nt * 4 + 1]);
                    *(float2*)(Gp + (row0 + 8) * 512 + b) = make_float2(acc[nt * 4 + 2], acc[nt * 4 + 3]);
                }
            } else {
                char* Gp = (role == 1) ? (half ? GX1 : GX0) : (half ? GH1 : GH0);
                int wb = (role == 1) ? (wl - 8) : (wl - 10);
#pragma unroll
                for (int nt = 0; nt < 4; nt++) {
                    int b = (4 * (wb * 32 + nt * 8 + tg * 2)) ^ swG;
                    *(float2*)(Gp + row0 * 256 + b)       = make_float2(acc[nt * 4 + 0], acc[nt * 4 + 1]);
                    *(float2*)(Gp + (row0 + 8) * 256 + b) = make_float2(acc[nt * 4 + 2], acc[nt * 4 + 3]);
                }
            }
        }
        __syncthreads();

        // ---- gates (+ L1: online-softmax attention); sum K-half partials ----
        for (int p = tid; p < MB * 32; p += NTH) {
            int row = p >> 5, jp = p & 31;
            int sw = (row & 7) << 5;
            int o = (8 * jp) ^ sw;
            float2 rva = *(float2*)(GRZ0 + row * 512 + o);
            float2 rvb = *(float2*)(GRZ1 + row * 512 + o);
            float2 zva = *(float2*)(GRZ0 + row * 512 + 256 + o);
            float2 zvb = *(float2*)(GRZ1 + row * 512 + 256 + o);
            float2 xva = *(float2*)(GX0 + row * 256 + o);
            float2 xvb = *(float2*)(GX1 + row * 256 + o);
            float2 hva = *(float2*)(GH0 + row * 256 + o);
            float2 hvb = *(float2*)(GH1 + row * 256 + o);
            float rx = rva.x + rvb.x, ry = rva.y + rvb.y;
            float zx = zva.x + zvb.x, zy = zva.y + zvb.y;
            float xx = xva.x + xvb.x, xy = xva.y + xvb.y;
            float hx = hva.x + hvb.x, hy = hva.y + hvb.y;
            int i0 = 2 * jp;
            float hp0 = hS[row * 64 + i0], hp1 = hS[row * 64 + i0 + 1];
            float r0 = sigmoid_fast(rx + bias[i0]);
            float r1 = sigmoid_fast(ry + bias[i0 + 1]);
            float z0 = sigmoid_fast(zx + bias[64 + i0]);
            float z1 = sigmoid_fast(zy + bias[64 + i0 + 1]);
            float n0 = tanh_fast(xx + bias[128 + i0]     + r0 * (hx + bias[192 + i0]));
            float n1 = tanh_fast(xy + bias[128 + i0 + 1] + r1 * (hy + bias[192 + i0 + 1]));
            float o0 = fmaf(z0, hp0 - n0, n0);
            float o1 = fmaf(z1, hp1 - n1, n1);
            hS[row * 64 + i0] = o0;
            hS[row * 64 + i0 + 1] = o1;
            u32 hip = pack2f(o0, o1);
            int ba = row * 256 + 128 + ((4 * jp) ^ ((row & 7) << 4));
            *(u32*)(AHI + ba) = hip;
            if (L == 0) {
                g_hap[((size_t)(node0 + row) * TT + t) * 32 + jp] = hip;
            } else {
                float sc = o0 * aw0 + o1 * aw1;
#pragma unroll
                for (int of = 16; of > 0; of >>= 1) sc += __shfl_xor_sync(0xffffffffu, sc, of);
                sc += ab;
                float m_old = mS[row];
                float mn = fmaxf(m_old, sc);
                float ea = __expf(m_old - mn);
                float eb = __expf(sc - mn);
                ctx[row * 64 + i0]     = ctx[row * 64 + i0]     * ea + eb * o0;
                ctx[row * 64 + i0 + 1] = ctx[row * 64 + i0 + 1] * ea + eb * o1;
                if (jp == 0) { mS[row] = mn; ZS[row] = ZS[row] * ea + eb; }
            }
        }
        // ---- overlap: stage next timestep's X while gates warps drain ----
        if (t + 1 < TT) stage_x(t + 1);
        __syncthreads();
    }

    if (L == 1) {
        float fw0 = fwS[2 * lid], fw1 = fwS[2 * lid + 1];
        for (int row = wid; row < MB; row += 24) {
            float v = ctx[row * 64 + 2 * lid] * fw0 + ctx[row * 64 + 2 * lid + 1] * fw1;
#pragma unroll
            for (int of = 16; of > 0; of >>= 1) v += __shfl_xor_sync(0xffffffffu, v, of);
            if (lid == 0) {
                int node = node0 + row;
                float last = x[((size_t)(TT - 1) * NN + node) * FIN];
                outv[node] = last + v / ZS[row] + fbp[0];
            }
        }
    }
}

// ---------------- launch ----------------------------------------------------
extern "C" void kernel_launch(void* const* d_in, const int* in_sizes, int n_in,
                              void* d_out, int out_size) {
    const float* x      = (const float*)d_in[0];
    const int*   ei     = (const int*)  d_in[1];
    const float* gcn_w  = (const float*)d_in[2];
    const float* gcn_b  = (const float*)d_in[3];
    const float* w_ih0  = (const float*)d_in[4];
    const float* w_hh0  = (const float*)d_in[5];
    const float* b_ih0  = (const float*)d_in[6];
    const float* b_hh0  = (const float*)d_in[7];
    const float* w_ih1  = (const float*)d_in[8];
    const float* w_hh1  = (const float*)d_in[9];
    const float* b_ih1  = (const float*)d_in[10];
    const float* b_hh1  = (const float*)d_in[11];
    const float* attn_w = (const float*)d_in[12];
    const float* attn_b = (const float*)d_in[13];
    const float* fc_w   = (const float*)d_in[14];
    const float* fc_b   = (const float*)d_in[15];
    float* out = (float*)d_out;

    cudaFuncSetAttribute(k_rec<0>, cudaFuncAttributeMaxDynamicSharedMemorySize, SMEM_L0);
    cudaFuncSetAttribute(k_rec<1>, cudaFuncAttributeMaxDynamicSharedMemorySize, SMEM_L1);

    k_deg_init<<<(NN + 255) / 256, 256>>>();
    k_deg_edge<<<(NE + 255) / 256, 256>>>(ei);
    k_agg_init<<<(NN * TT * 2 + 255) / 256, 256>>>(x);
    k_edge_agg<<<(NE * 32 + 255) / 256, 256>>>(ei, x);

    k_rec<0><<<GRID_REC, NTH, SMEM_L0>>>(w_ih0, w_hh0, b_ih0, b_hh0,
                                         gcn_w, gcn_b, nullptr, nullptr, nullptr, nullptr,
                                         x, nullptr);
    k_rec<1><<<GRID_REC, NTH, SMEM_L1>>>(w_ih1, w_hh1, b_ih1, b_hh1,
                                         nullptr, nullptr, attn_w, attn_b, fc_w, fc_b,
                                         x, out);
}

// round 15
// speedup vs baseline: 2.1280x; 1.0198x over previous
#include <cuda_runtime.h>
#include <cuda_bf16.h>
#include <math.h>

#define NN 10000      // nodes
#define TT 12         // seq len
#define FIN 16        // in channels
#define HH 64         // hidden
#define K3 192        // 3*H
#define NE 160000     // edges
#define NT (NN*TT)    // 120000 rows
#define MB 80         // nodes per block (10000 = 125 * 80)
#define GRID_REC 125
#define NTH 768       // 24 warps: 2 K-halves x 12 N-role warps

typedef unsigned int u32;
typedef unsigned long long u64;

// ---------------- scratch (device globals; no allocation allowed) ----------
__device__ float g_deg[NN];
__device__ u32  g_aggh[NN * TT * 8];         // packed bf16 agg: 16 per (n,t) row
__device__ u32  g_xbf [NN * TT * 8];         // packed bf16 x, t-major (t*NN+n)
__device__ u32  g_hap[NN * TT * (HH / 2)];   // packed bf16 hi-pairs (h1)

// ---------------- helpers ----------------------------------------------------
__device__ __forceinline__ float tanh_fast(float x) {
    float y; asm("tanh.approx.f32 %0, %1;" : "=f"(y) : "f"(x)); return y;
}
__device__ __forceinline__ float sigmoid_fast(float x) {
    return fmaf(0.5f, tanh_fast(0.5f * x), 0.5f);
}
__device__ __forceinline__ u32 pack2(__nv_bfloat16 a, __nv_bfloat16 b) {
    return (u32)__bfloat16_as_ushort(a) | ((u32)__bfloat16_as_ushort(b) << 16);
}
__device__ __forceinline__ u32 pack2f(float a, float b) {
    return pack2(__float2bfloat16(a), __float2bfloat16(b));
}
__device__ __forceinline__ void unp2(u32 p, float& a, float& b) {
    a = __bfloat162float(__ushort_as_bfloat16((unsigned short)(p & 0xffffu)));
    b = __bfloat162float(__ushort_as_bfloat16((unsigned short)(p >> 16)));
}
__device__ __forceinline__ u32 mulbf2(u32 a, u32 b) {
    u32 r; asm("mul.bf16x2 %0, %1, %2;" : "=r"(r) : "r"(a), "r"(b)); return r;
}
__device__ __forceinline__ void mma16816(float* c, const u32* a, u32 b0, u32 b1) {
    asm volatile(
        "mma.sync.aligned.m16n8k16.row.col.f32.bf16.bf16.f32 "
        "{%0,%1,%2,%3}, {%4,%5,%6,%7}, {%8,%9}, {%0,%1,%2,%3};"
        : "+f"(c[0]), "+f"(c[1]), "+f"(c[2]), "+f"(c[3])
        : "r"(a[0]), "r"(a[1]), "r"(a[2]), "r"(a[3]), "r"(b0), "r"(b1));
}
__device__ __forceinline__ void ldm4(u32* r, u32 saddr) {
    asm volatile("ldmatrix.sync.aligned.m8n8.x4.shared.b16 {%0,%1,%2,%3}, [%4];"
                 : "=r"(r[0]), "=r"(r[1]), "=r"(r[2]), "=r"(r[3]) : "r"(saddr));
}

// ---------------- degree / prep --------------------------------------------
__global__ void k_deg_init() {
    int i = blockIdx.x * blockDim.x + threadIdx.x;
    if (i < NN) g_deg[i] = 1.0f;
}
__global__ void k_deg_edge(const int* __restrict__ ei) {
    int e = blockIdx.x * blockDim.x + threadIdx.x;
    if (e < NE) atomicAdd(&g_deg[ei[NE + e]], 1.0f);
}
// agg init + x bf16 pre-convert. t-major indexing: coalesced x read + xbf write.
__global__ void k_agg_init(const float* __restrict__ x) {
    int idx = blockIdx.x * blockDim.x + threadIdx.x;   // (t,n,q) t-major
    if (idx >= NN * TT * 2) return;
    int q = idx & 1;
    int tn = idx >> 1;
    int n = tn % NN, t = tn / NN;
    const float4* xr = reinterpret_cast<const float4*>(&x[((size_t)tn * 16) + q * 8]);
    float4 v0 = xr[0], v1 = xr[1];
    // raw bf16 copy (unscaled) for edge kernel
    uint4 raw;
    raw.x = pack2f(v0.x, v0.y);
    raw.y = pack2f(v0.z, v0.w);
    raw.z = pack2f(v1.x, v1.y);
    raw.w = pack2f(v1.z, v1.w);
    reinterpret_cast<uint4*>(g_xbf)[idx] = raw;
    // self-loop init term, scaled by 1/deg
    float di = rsqrtf(g_deg[n]);
    float c = di * di;
    uint4 o;
    o.x = pack2f(v0.x * c, v0.y * c);
    o.y = pack2f(v0.z * c, v0.w * c);
    o.z = pack2f(v1.x * c, v1.y * c);
    o.w = pack2f(v1.z * c, v1.w * c);
    reinterpret_cast<uint4*>(g_aggh)[(size_t)n * (TT * 2) + t * 2 + q] = o;
}
// edge scatter: thread = (edge, chunk), 24 chunks/edge, full utilization.
__global__ void k_edge_agg(const int* __restrict__ ei) {
    int gt = blockIdx.x * blockDim.x + threadIdx.x;
    int e = gt / 24, ch = gt - e * 24;
    if (e >= NE) return;
    int s = ei[e];
    int d = ei[NE + e];
    float c = rsqrtf(g_deg[s]) * rsqrtf(g_deg[d]);
    u32 cc = pack2f(c, c);
    int t = ch >> 1, qh = ch & 1;
    uint4 v = reinterpret_cast<const uint4*>(g_xbf)[((size_t)t * NN + s) * 2 + qh];
    u32 p0 = mulbf2(v.x, cc);
    u32 p1 = mulbf2(v.y, cc);
    u32 p2 = mulbf2(v.z, cc);
    u32 p3 = mulbf2(v.w, cc);
    u32* dst = g_aggh + (size_t)d * (TT * 8) + ch * 4;
    asm volatile("red.global.add.noftz.v4.bf16x2 [%0], {%1, %2, %3, %4};"
                 :: "l"(dst), "r"(p0), "r"(p1), "r"(p2), "r"(p3) : "memory");
}

// ---------------- fused HMMA GRU layers --------------------------------------
// 24 warps = 2 K-halves x {8 rz + 2 xn + 2 hn}. Single-term bf16 weights.
#define OFF_AHI  0               // bf16 A tile [80 x 256B]: X half | H half
#define OFF_GRZ0 20480           // fp32 [80][128] swizzled, K-half 0
#define OFF_GRZ1 61440           // K-half 1
#define OFF_GX0  102400          // fp32 [80][64]
#define OFF_GX1  122880
#define OFF_GH0  143360
#define OFF_GH1  163840
#define OFF_HS   184320          // fp32 h state [80][64]
#define OFF_B    204800          // biases: 256 floats
#define OFF_EXT  205824
#define SMEM_L0 (OFF_EXT + 4096 + 256)
#define SMEM_L1 (OFF_EXT + 20480 + 640 + 256 + 256 + 16)

// single-term m-tile: acc += a * b
template<int KKS, int NTS>
__device__ __forceinline__ void mma_m_tile(
    u32 a_base, int kbyte, int swrow, int kk0,
    const u32* bh, float* acc)
{
#pragma unroll
    for (int q = 0; q < NTS * 4; q++) acc[q] = 0.f;
#pragma unroll
    for (int kk = 0; kk < KKS; kk++) {
        u32 off = (u32)((((kk + kk0) * 32) + kbyte) ^ swrow);
        u32 ah[4];
        ldm4(ah, a_base + off);
#pragma unroll
        for (int nt = 0; nt < NTS; nt++) {
            int f = kk * NTS + nt;
            mma16816(acc + nt * 4, ah, bh[2 * f], bh[2 * f + 1]);
        }
    }
}

template<int L>
__global__ __launch_bounds__(NTH, 1) void k_rec(
    const float* __restrict__ wih, const float* __restrict__ whh,
    const float* __restrict__ bih, const float* __restrict__ bhh,
    const float* __restrict__ gwp, const float* __restrict__ gbp,
    const float* __restrict__ awp, const float* __restrict__ abp,
    const float* __restrict__ fwp, const float* __restrict__ fbp,
    const float* __restrict__ x,   float* __restrict__ outv)
{
    extern __shared__ __align__(16) char sm[];
    char* AHI  = sm + OFF_AHI;
    char* GRZ0 = sm + OFF_GRZ0;
    char* GRZ1 = sm + OFF_GRZ1;
    char* GX0  = sm + OFF_GX0;
    char* GX1  = sm + OFF_GX1;
    char* GH0  = sm + OFF_GH0;
    char* GH1  = sm + OFF_GH1;
    float* hS   = (float*)(sm + OFF_HS);
    float* bias = (float*)(sm + OFF_B);
    float* gwS = (float*)(sm + OFF_EXT);
    float* gbS = (float*)(sm + OFF_EXT + 4096);
    float* ctx = (float*)(sm + OFF_EXT);
    float* mS  = (float*)(sm + OFF_EXT + 20480);
    float* ZS  = (float*)(sm + OFF_EXT + 20480 + 320);
    float* awS = (float*)(sm + OFF_EXT + 21120);
    float* fwS = (float*)(sm + OFF_EXT + 21376);
    float* scS = (float*)(sm + OFF_EXT + 21632);

    int tid = threadIdx.x, wid = tid >> 5, lid = tid & 31;
    int g = lid >> 2, tg = lid & 3;
    int node0 = blockIdx.x * MB;
    int wl = wid % 12;          // N-role warp index
    int half = wid / 12;        // K-half

    if (tid < 128) bias[tid] = bih[tid] + bhh[tid];
    else if (tid < 192) bias[tid] = bih[tid];
    else if (tid < 256) bias[tid] = bhh[tid - 64];

    if (L == 0) {
        for (int i = tid; i < FIN * HH; i += NTH) gwS[i] = gwp[i];
        if (tid >= 256 && tid < 320) gbS[tid - 256] = gbp[tid - 256];
    } else {
        for (int i = tid; i < MB * 64; i += NTH) ctx[i] = 0.0f;
        if (tid >= 256 && tid < 256 + MB) { mS[tid - 256] = -3.0e38f; ZS[tid - 256] = 0.0f; }
        if (tid >= 384 && tid < 448) { awS[tid - 384] = awp[tid - 384]; fwS[tid - 384] = fwp[tid - 384]; }
        if (tid == 448) scS[0] = abp[0];
    }

    {
        uint4 z = make_uint4(0, 0, 0, 0);
        for (int i = tid; i < 1280; i += NTH) ((uint4*)AHI)[i] = z;
        for (int i = tid; i < MB * 64; i += NTH) hS[i] = 0.0f;
    }

    bool is_rz = wl < 8;
    int role = is_rz ? 0 : (wl < 10 ? 1 : 2);
    int kk0 = is_rz ? half * 4 : half * 2;

    // persistent B fragments: bf16 weights, 8 slots x 2 regs
    u32 bh[16];
#pragma unroll
    for (int f = 0; f < 8; f++) {
        int kk = is_rz ? (f >> 1) : (f >> 2);
        int nt = is_rz ? (f & 1)  : (f & 3);
        int nrow;
        if (role == 0)      nrow = wl * 16 + nt * 8 + g;
        else if (role == 1) nrow = 128 + (wl - 8) * 32 + nt * 8 + g;
        else                nrow = 128 + (wl - 10) * 32 + nt * 8 + g;
#pragma unroll
        for (int r = 0; r < 2; r++) {
            int k = (kk + kk0) * 16 + tg * 2 + r * 8;
            float w0, w1;
            if (role == 0) {
                if (k < 64) { w0 = wih[nrow * 64 + k];      w1 = wih[nrow * 64 + k + 1]; }
                else        { w0 = whh[nrow * 64 + k - 64]; w1 = whh[nrow * 64 + k - 63]; }
            } else if (role == 1) {
                w0 = wih[nrow * 64 + k]; w1 = wih[nrow * 64 + k + 1];
            } else {
                w0 = whh[nrow * 64 + k]; w1 = whh[nrow * 64 + k + 1];
            }
            bh[2 * f + r] = pack2f(w0, w1);
        }
    }

    int aoff = (role == 2) ? 128 : 0;
    int quad = lid >> 3;
    int rloc = (lid & 7) + ((quad & 1) << 3);
    int kbyte = (quad >> 1) << 4;
    int swrow = (rloc & 7) << 4;
    u32 AHI_s = (u32)__cvta_generic_to_shared(AHI);

    float aw0 = 0.f, aw1 = 0.f, ab = 0.f;
    __syncthreads();
    if (L == 1) { aw0 = awS[2 * lid]; aw1 = awS[2 * lid + 1]; ab = scS[0]; }

    // stage X(tt) into the X half of the A tile (bf16, swizzled)
    auto stage_x = [&](int tt) {
        if (L == 0) {
            for (int i = tid; i < MB * 16; i += NTH) {
                int m = i >> 4, j = i & 15;
                const uint4* ar = reinterpret_cast<const uint4*>(
                    g_aggh + (((size_t)(node0 + m)) * TT + tt) * 8);
                uint4 qa = ar[0], qb = ar[1];
                float a[16];
                unp2(qa.x, a[0], a[1]);  unp2(qa.y, a[2], a[3]);
                unp2(qa.z, a[4], a[5]);  unp2(qa.w, a[6], a[7]);
                unp2(qb.x, a[8], a[9]);  unp2(qb.y, a[10], a[11]);
                unp2(qb.z, a[12], a[13]); unp2(qb.w, a[14], a[15]);
                float s0 = gbS[4 * j], s1 = gbS[4 * j + 1], s2 = gbS[4 * j + 2], s3 = gbS[4 * j + 3];
#pragma unroll
                for (int f = 0; f < 16; f++) {
                    const float4 wv = reinterpret_cast<const float4*>(gwS)[f * 16 + j];
                    s0 = fmaf(a[f], wv.x, s0);
                    s1 = fmaf(a[f], wv.y, s1);
                    s2 = fmaf(a[f], wv.z, s2);
                    s3 = fmaf(a[f], wv.w, s3);
                }
                s0 = fmaxf(s0, 0.f); s1 = fmaxf(s1, 0.f);
                s2 = fmaxf(s2, 0.f); s3 = fmaxf(s3, 0.f);
                uint2 phv;
                phv.x = pack2f(s0, s1);
                phv.y = pack2f(s2, s3);
                int byt = m * 256 + ((8 * j) ^ ((m & 7) << 4));
                *(uint2*)(AHI + byt) = phv;
            }
        } else {
            const uint2* in8 = reinterpret_cast<const uint2*>(g_hap);
            for (int i = tid; i < MB * 16; i += NTH) {
                int m = i >> 4, j = i & 15;
                uint2 v = in8[((size_t)(node0 + m) * TT + tt) * 16 + j];
                int byt = m * 256 + ((8 * j) ^ ((m & 7) << 4));
                *(uint2*)(AHI + byt) = v;
            }
        }
    };

    stage_x(0);
    __syncthreads();

    for (int t = 0; t < TT; t++) {
        // ---- MMA: 5 m-tiles of 16 rows, each warp its K-half ----
        for (int m = 0; m < 5; m++) {
            float acc[16];
            u32 rowb = (u32)((m * 16 + rloc) * 256 + aoff);
            if (is_rz) mma_m_tile<4, 2>(AHI_s + rowb, kbyte, swrow, kk0, bh, acc);
            else       mma_m_tile<2, 4>(AHI_s + rowb, kbyte, swrow, kk0, bh, acc);

            int row0 = m * 16 + g;
            int swG = g << 5;
            if (role == 0) {
                char* Gp = half ? GRZ1 : GRZ0;
#pragma unroll
                for (int nt = 0; nt < 2; nt++) {
                    int b = (4 * (wl * 16 + nt * 8 + tg * 2)) ^ swG;
                    *(float2*)(Gp + row0 * 512 + b)       = make_float2(acc[nt * 4 + 0], acc[nt * 4 + 1]);
                    *(float2*)(Gp + (row0 + 8) * 512 + b) = make_float2(acc[nt * 4 + 2], acc[nt * 4 + 3]);
                }
            } else {
                char* Gp = (role == 1) ? (half ? GX1 : GX0) : (half ? GH1 : GH0);
                int wb = (role == 1) ? (wl - 8) : (wl - 10);
#pragma unroll
                for (int nt = 0; nt < 4; nt++) {
                    int b = (4 * (wb * 32 + nt * 8 + tg * 2)) ^ swG;
                    *(float2*)(Gp + row0 * 256 + b)       = make_float2(acc[nt * 4 + 0], acc[nt * 4 + 1]);
                    *(float2*)(Gp + (row0 + 8) * 256 + b) = make_float2(acc[nt * 4 + 2], acc[nt * 4 + 3]);
                }
            }
        }
        __syncthreads();

        // ---- gates (+ L1: online-softmax attention); sum K-half partials ----
        for (int p = tid; p < MB * 32; p += NTH) {
            int row = p >> 5, jp = p & 31;
            int sw = (row & 7) << 5;
            int o = (8 * jp) ^ sw;
            float2 rva = *(float2*)(GRZ0 + row * 512 + o);
            float2 rvb = *(float2*)(GRZ1 + row * 512 + o);
            float2 zva = *(float2*)(GRZ0 + row * 512 + 256 + o);
            float2 zvb = *(float2*)(GRZ1 + row * 512 + 256 + o);
            float2 xva = *(float2*)(GX0 + row * 256 + o);
            float2 xvb = *(float2*)(GX1 + row * 256 + o);
            float2 hva = *(float2*)(GH0 + row * 256 + o);
            float2 hvb = *(float2*)(GH1 + row * 256 + o);
            float rx = rva.x + rvb.x, ry = rva.y + rvb.y;
            float zx = zva.x + zvb.x, zy = zva.y + zvb.y;
            float xx = xva.x + xvb.x, xy = xva.y + xvb.y;
            float hx = hva.x + hvb.x, hy = hva.y + hvb.y;
            int i0 = 2 * jp;
            float hp0 = hS[row * 64 + i0], hp1 = hS[row * 64 + i0 + 1];
            float r0 = sigmoid_fast(rx + bias[i0]);
            float r1 = sigmoid_fast(ry + bias[i0 + 1]);
            float z0 = sigmoid_fast(zx + bias[64 + i0]);
            float z1 = sigmoid_fast(zy + bias[64 + i0 + 1]);
            float n0 = tanh_fast(xx + bias[128 + i0]     + r0 * (hx + bias[192 + i0]));
            float n1 = tanh_fast(xy + bias[128 + i0 + 1] + r1 * (hy + bias[192 + i0 + 1]));
            float o0 = fmaf(z0, hp0 - n0, n0);
            float o1 = fmaf(z1, hp1 - n1, n1);
            hS[row * 64 + i0] = o0;
            hS[row * 64 + i0 + 1] = o1;
            u32 hip = pack2f(o0, o1);
            int ba = row * 256 + 128 + ((4 * jp) ^ ((row & 7) << 4));
            *(u32*)(AHI + ba) = hip;
            if (L == 0) {
                g_hap[((size_t)(node0 + row) * TT + t) * 32 + jp] = hip;
            } else {
                float sc = o0 * aw0 + o1 * aw1;
#pragma unroll
                for (int of = 16; of > 0; of >>= 1) sc += __shfl_xor_sync(0xffffffffu, sc, of);
                sc += ab;
                float m_old = mS[row];
                float mn = fmaxf(m_old, sc);
                float ea = __expf(m_old - mn);
                float eb = __expf(sc - mn);
                ctx[row * 64 + i0]     = ctx[row * 64 + i0]     * ea + eb * o0;
                ctx[row * 64 + i0 + 1] = ctx[row * 64 + i0 + 1] * ea + eb * o1;
                if (jp == 0) { mS[row] = mn; ZS[row] = ZS[row] * ea + eb; }
            }
        }
        // ---- overlap: stage next timestep's X while gates warps drain ----
        if (t + 1 < TT) stage_x(t + 1);
        __syncthreads();
    }

    if (L == 1) {
        float fw0 = fwS[2 * lid], fw1 = fwS[2 * lid + 1];
        for (int row = wid; row < MB; row += 24) {
            float v = ctx[row * 64 + 2 * lid] * fw0 + ctx[row * 64 + 2 * lid + 1] * fw1;
#pragma unroll
            for (int of = 16; of > 0; of >>= 1) v += __shfl_xor_sync(0xffffffffu, v, of);
            if (lid == 0) {
                int node = node0 + row;
                float last = x[((size_t)(TT - 1) * NN + node) * FIN];
                outv[node] = last + v / ZS[row] + fbp[0];
            }
        }
    }
}

// ---------------- launch ----------------------------------------------------
extern "C" void kernel_launch(void* const* d_in, const int* in_sizes, int n_in,
                              void* d_out, int out_size) {
    const float* x      = (const float*)d_in[0];
    const int*   ei     = (const int*)  d_in[1];
    const float* gcn_w  = (const float*)d_in[2];
    const float* gcn_b  = (const float*)d_in[3];
    const float* w_ih0  = (const float*)d_in[4];
    const float* w_hh0  = (const float*)d_in[5];
    const float* b_ih0  = (const float*)d_in[6];
    const float* b_hh0  = (const float*)d_in[7];
    const float* w_ih1  = (const float*)d_in[8];
    const float* w_hh1  = (const float*)d_in[9];
    const float* b_ih1  = (const float*)d_in[10];
    const float* b_hh1  = (const float*)d_in[11];
    const float* attn_w = (const float*)d_in[12];
    const float* attn_b = (const float*)d_in[13];
    const float* fc_w   = (const float*)d_in[14];
    const float* fc_b   = (const float*)d_in[15];
    float* out = (float*)d_out;

    cudaFuncSetAttribute(k_rec<0>, cudaFuncAttributeMaxDynamicSharedMemorySize, SMEM_L0);
    cudaFuncSetAttribute(k_rec<1>, cudaFuncAttributeMaxDynamicSharedMemorySize, SMEM_L1);

    k_deg_init<<<(NN + 255) / 256, 256>>>();
    k_deg_edge<<<(NE + 255) / 256, 256>>>(ei);
    k_agg_init<<<(NN * TT * 2 + 255) / 256, 256>>>(x);
    k_edge_agg<<<(NE * 24 + 255) / 256, 256>>>(ei);

    k_rec<0><<<GRID_REC, NTH, SMEM_L0>>>(w_ih0, w_hh0, b_ih0, b_hh0,
                                         gcn_w, gcn_b, nullptr, nullptr, nullptr, nullptr,
                                         x, nullptr);
    k_rec<1><<<GRID_REC, NTH, SMEM_L1>>>(w_ih1, w_hh1, b_ih1, b_hh1,
                                         nullptr, nullptr, attn_w, attn_b, fc_w, fc_b,
                                         x, out);
}